// round 11
// baseline (speedup 1.0000x reference)
#include <cuda_runtime.h>
#include <cuda_fp16.h>
#include <cstdint>

// ---------------- problem constants ----------------
#define NB      2048
#define NA      64
#define NATOMS  (NB*NA)
#define AEV     384
#define N0      160
#define N1      128
#define N2      96
#define NTYPES  4
#define TILE    64
#define MAXTILES 2056

// ---------------- device scratch ----------------
__device__ int   g_is64;
__device__ int   g_counts[NTYPES];
__device__ int   g_cursor[NTYPES];
__device__ int   g_perm[NATOMS];

// fragment-layout fp16 weight images: [type][ks][n8tile][lane] as uint2
// (uint2.x = {W[kb][n],W[kb+1][n]}, uint2.y = {W[kb+8][n],W[kb+9][n]},
//  kb = ks*16 + (lane&3)*2, n = ntile*8 + lane/4)
#define W0_KS 24
#define W0_NT 20
#define W1_KS 10
#define W1_NT 16
#define W2_KS 8
#define W2_NT 12
#define PF_W0 (NTYPES*W0_KS*W0_NT*32)   // 61440
#define PF_W1 (NTYPES*W1_KS*W1_NT*32)   // 20480
#define PF_W2 (NTYPES*W2_KS*W2_NT*32)   // 12288
__device__ uint2 g_W0frag[PF_W0];
__device__ uint2 g_W1frag[PF_W1];
__device__ uint2 g_W2frag[PF_W2];

__device__ __forceinline__ float celu_f(float x) {
    return x > 0.f ? x : 0.1f * (__expf(10.f * x) - 1.f);
}
__device__ __forceinline__ __half2 celu_h2(__half2 x) {
    const __half2 ZERO  = __float2half2_rn(0.f);
    const __half2 ONE   = __float2half2_rn(1.f);
    const __half2 TEN   = __float2half2_rn(10.f);
    const __half2 TENTH = __float2half2_rn(0.1f);
    __half2 xa  = __hmin2(x, ZERO);
    __half2 ex  = h2exp(__hmul2(xa, TEN));
    __half2 neg = __hmul2(__hsub2(ex, ONE), TENTH);
    __half2 m   = __hgt2(x, ZERO);
    return __hfma2(m, __hsub2(x, neg), neg);
}
__device__ __forceinline__ int get_sp(const int* __restrict__ raw, int i, int is64) {
    return is64 ? raw[2 * i] : raw[i];
}
__device__ __forceinline__ uint32_t pack2h(float a, float b) {
    __half ha = __float2half_rn(a), hb = __float2half_rn(b);
    return (uint32_t)__half_as_ushort(ha) | ((uint32_t)__half_as_ushort(hb) << 16);
}
__device__ __forceinline__ uint32_t smem_u32(const void* p) {
    uint32_t a;
    asm("{ .reg .u64 t; cvta.to.shared.u64 t, %1; cvt.u32.u64 %0, t; }" : "=r"(a) : "l"(p));
    return a;
}
__device__ __forceinline__ void ldm_x4(uint32_t* r, uint32_t addr) {
    asm volatile("ldmatrix.sync.aligned.m8n8.x4.shared.b16 {%0,%1,%2,%3}, [%4];"
                 : "=r"(r[0]), "=r"(r[1]), "=r"(r[2]), "=r"(r[3]) : "r"(addr));
}
__device__ __forceinline__ void mma_fp16(float* d, const uint32_t* a, const uint32_t* b) {
    asm volatile(
        "mma.sync.aligned.m16n8k16.row.col.f32.f16.f16.f32 "
        "{%0,%1,%2,%3},{%4,%5,%6,%7},{%8,%9},{%0,%1,%2,%3};"
        : "+f"(d[0]), "+f"(d[1]), "+f"(d[2]), "+f"(d[3])
        : "r"(a[0]), "r"(a[1]), "r"(a[2]), "r"(a[3]), "r"(b[0]), "r"(b[1]));
}
__device__ __forceinline__ void mma_fp16_u2(float* d, const uint32_t* a, const uint2& b) {
    asm volatile(
        "mma.sync.aligned.m16n8k16.row.col.f32.f16.f16.f32 "
        "{%0,%1,%2,%3},{%4,%5,%6,%7},{%8,%9},{%0,%1,%2,%3};"
        : "+f"(d[0]), "+f"(d[1]), "+f"(d[2]), "+f"(d[3])
        : "r"(a[0]), "r"(a[1]), "r"(a[2]), "r"(a[3]), "r"(b.x), "r"(b.y));
}

// ---------------- launch 1: dtype probe + reset ----------------
__global__ void k_detect(const int* __restrict__ sp_raw) {
    if (threadIdx.x == 0) {
        int odd_nonzero = 0;
        #pragma unroll
        for (int i = 1; i < 64; i += 2) odd_nonzero |= (sp_raw[i] != 0);
        g_is64 = odd_nonzero ? 0 : 1;
    }
    if (threadIdx.x < NTYPES) { g_counts[threadIdx.x] = 0; g_cursor[threadIdx.x] = 0; }
}

// ---------------- launch 2: count + fragment weight prep (fused) ----------------
#define CP_GRID (NATOMS / 256)   // 512 blocks; prep needs 94208 < 131072 threads

__global__ void k_count_prep(const int* __restrict__ sp,
                             const float* __restrict__ W0, const float* __restrict__ W1,
                             const float* __restrict__ W2) {
    int gid = blockIdx.x * blockDim.x + threadIdx.x;

    __shared__ int c[NTYPES];
    if (threadIdx.x < NTYPES) c[threadIdx.x] = 0;
    __syncthreads();
    if (gid < NATOMS) {
        int t = get_sp(sp, gid, g_is64);
        if ((unsigned)t < NTYPES) atomicAdd(&c[t], 1);
    }
    __syncthreads();
    if (threadIdx.x < NTYPES && c[threadIdx.x]) atomicAdd(&g_counts[threadIdx.x], c[threadIdx.x]);

    int idx = gid;
    if (idx < PF_W0) {
        int t = idx / (W0_KS * W0_NT * 32), r = idx % (W0_KS * W0_NT * 32);
        int ks = r / (W0_NT * 32); r %= (W0_NT * 32);
        int ntile = r / 32, lane = r % 32;
        int kb = ks * 16 + (lane & 3) * 2;
        int n  = ntile * 8 + (lane >> 2);
        uint2 v;
        v.x = pack2h(W0[((size_t)t * AEV + kb)     * N0 + n], W0[((size_t)t * AEV + kb + 1) * N0 + n]);
        v.y = pack2h(W0[((size_t)t * AEV + kb + 8) * N0 + n], W0[((size_t)t * AEV + kb + 9) * N0 + n]);
        g_W0frag[idx] = v;
    } else if (idx < PF_W0 + PF_W1) {
        int j = idx - PF_W0;
        int t = j / (W1_KS * W1_NT * 32), r = j % (W1_KS * W1_NT * 32);
        int ks = r / (W1_NT * 32); r %= (W1_NT * 32);
        int ntile = r / 32, lane = r % 32;
        int kb = ks * 16 + (lane & 3) * 2;
        int n  = ntile * 8 + (lane >> 2);
        uint2 v;
        v.x = pack2h(W1[((size_t)t * N0 + kb)     * N1 + n], W1[((size_t)t * N0 + kb + 1) * N1 + n]);
        v.y = pack2h(W1[((size_t)t * N0 + kb + 8) * N1 + n], W1[((size_t)t * N0 + kb + 9) * N1 + n]);
        g_W1frag[j] = v;
    } else if (idx < PF_W0 + PF_W1 + PF_W2) {
        int j = idx - PF_W0 - PF_W1;
        int t = j / (W2_KS * W2_NT * 32), r = j % (W2_KS * W2_NT * 32);
        int ks = r / (W2_NT * 32); r %= (W2_NT * 32);
        int ntile = r / 32, lane = r % 32;
        int kb = ks * 16 + (lane & 3) * 2;
        int n  = ntile * 8 + (lane >> 2);
        uint2 v;
        v.x = pack2h(W2[((size_t)t * N1 + kb)     * N2 + n], W2[((size_t)t * N1 + kb + 1) * N2 + n]);
        v.y = pack2h(W2[((size_t)t * N1 + kb + 8) * N2 + n], W2[((size_t)t * N1 + kb + 9) * N2 + n]);
        g_W2frag[j] = v;
    }
}

// ---------------- launch 3: scatter + output-head + out_e zero ----------------
__global__ void k_scatter(const int* __restrict__ sp,
                          float* __restrict__ out_head,
                          float* __restrict__ out_e) {
    __shared__ int soff[NTYPES];
    __shared__ int base[NTYPES];
    __shared__ int lc[NTYPES];
    if (threadIdx.x == 0) {
        int o = 0;
        #pragma unroll
        for (int t = 0; t < NTYPES; t++) { soff[t] = o; o += g_counts[t]; }
    }
    if (threadIdx.x < NTYPES) lc[threadIdx.x] = 0;
    __syncthreads();
    int i = blockIdx.x * blockDim.x + threadIdx.x;
    if (i < NB) out_e[i] = 0.f;
    int t = -1, r = 0;
    if (i < NATOMS) {
        int tv = get_sp(sp, i, g_is64);
        if (out_head) out_head[i] = (float)tv;
        if ((unsigned)tv < NTYPES) { t = tv; r = atomicAdd(&lc[t], 1); }
    }
    __syncthreads();
    if (threadIdx.x < NTYPES)
        base[threadIdx.x] = lc[threadIdx.x] ? atomicAdd(&g_cursor[threadIdx.x], lc[threadIdx.x]) : 0;
    __syncthreads();
    if (t >= 0) g_perm[soff[t] + base[t] + r] = i;
}

// ---------------- launch 4: fused MLP (B via fragment LDG, double-buffered X) ----------------
// SMEM (bytes): BIAS 0..1936 | SIDX 1936..2192 | X[2] @2560 (2x13312) | H0 @29184 (21504) | H1 @50688 (17408)
#define BIAS_OFF 0
#define SIDX_OFF 1936
#define X_OFF    2560
#define XBUF_SZ  13312
#define H0_OFF   29184
#define H1_OFF   50688
#define SM_TOTAL 68096

__global__ __launch_bounds__(256, 3)
void k_mlp_tc(const float* __restrict__ aev,
              const float* __restrict__ b0, const float* __restrict__ b1,
              const float* __restrict__ b2, const float* __restrict__ W3,
              const float* __restrict__ b3,
              float* __restrict__ out_e)
{
    // derive this CTA's tile (type, start, len) from g_counts
    int t = -1, gstart = 0, len = 0;
    {
        int rem = blockIdx.x, off = 0;
        #pragma unroll
        for (int tt = 0; tt < NTYPES; tt++) {
            int cc = g_counts[tt];
            int ntl = (cc + TILE - 1) / TILE;
            if (t < 0) {
                if (rem < ntl) {
                    t = tt;
                    gstart = off + rem * TILE;
                    int l = cc - rem * TILE;
                    len = l < TILE ? l : TILE;
                } else rem -= ntl;
            }
            off += cc;
        }
    }
    if (t < 0) return;

    extern __shared__ char smem[];
    const uint32_t sb = smem_u32(smem);
    float* sBias = (float*)(smem + BIAS_OFF);
    int*   sIdx  = (int*)(smem + SIDX_OFF);

    const int tid  = threadIdx.x;
    const int lane = tid & 31;
    const int w    = tid >> 5;
    const int mw   = w & 1;         // M group (0/1)
    const int nww  = w >> 1;        // N group (0..3)
    const int mb   = mw * 32;

    if (tid < TILE) sIdx[tid] = (tid < len) ? g_perm[gstart + tid] : -1;
    for (int i = tid; i < N0; i += 256) sBias[i] = b0[t * N0 + i];
    for (int i = tid; i < N1; i += 256) sBias[160 + i] = b1[t * N1 + i];
    for (int i = tid; i < N2; i += 256) { sBias[288 + i] = b2[t * N2 + i]; sBias[384 + i] = W3[t * N2 + i]; }
    if (tid == 0) sBias[480] = b3[t];
    __syncthreads();   // sIdx visible for staging

    // stage X chunk 0 into buffer 0
    const int srow  = tid >> 2;
    const int scol0 = (tid & 3) * 24;
    const int sgi   = sIdx[srow];
    {
        const float4* src = (const float4*)(aev + (size_t)(sgi < 0 ? 0 : sgi) * AEV + scol0);
        char* dx = smem + X_OFF + srow * 208 + scol0 * 2;
        #pragma unroll
        for (int i = 0; i < 6; i++) {
            float4 v = (sgi >= 0) ? src[i] : make_float4(0.f, 0.f, 0.f, 0.f);
            *(__half2*)(dx + i * 8)     = __floats2half2_rn(v.x, v.y);
            *(__half2*)(dx + i * 8 + 4) = __floats2half2_rn(v.z, v.w);
        }
    }
    __syncthreads();

    // lane offsets for ldmatrix (A operand only)
    const int arow = (lane & 7) + (lane & 8);
    const int akb  = (lane & 16) ? 16 : 0;
    const uint32_t aXbase = sb + X_OFF + (mb + arow) * 208 + akb;

    // ===================== LAYER 0: 384 -> 160 =====================
    float acc0[2][5][4];
    #pragma unroll
    for (int mt = 0; mt < 2; mt++)
        #pragma unroll
        for (int nt = 0; nt < 5; nt++)
            #pragma unroll
            for (int q = 0; q < 4; q++) acc0[mt][nt][q] = 0.f;

    const uint2* W0f = g_W0frag + ((size_t)t * W0_KS * W0_NT + nww * 5) * 32 + lane;
    uint2 Bf[2][5];
    #pragma unroll
    for (int i = 0; i < 5; i++) Bf[0][i] = W0f[i * 32];

    for (int c = 0; c < 4; c++) {
        // stage next X chunk into the other buffer (overlaps MMA below)
        if (c < 3) {
            const float4* src = (const float4*)(aev + (size_t)(sgi < 0 ? 0 : sgi) * AEV + (c + 1) * 96 + scol0);
            char* dx = smem + X_OFF + ((c + 1) & 1) * XBUF_SZ + srow * 208 + scol0 * 2;
            #pragma unroll
            for (int i = 0; i < 6; i++) {
                float4 v = (sgi >= 0) ? src[i] : make_float4(0.f, 0.f, 0.f, 0.f);
                *(__half2*)(dx + i * 8)     = __floats2half2_rn(v.x, v.y);
                *(__half2*)(dx + i * 8 + 4) = __floats2half2_rn(v.z, v.w);
            }
        }
        const uint32_t aXb = aXbase + (c & 1) * XBUF_SZ;
        #pragma unroll
        for (int kss = 0; kss < 6; kss++) {
            const int ks  = c * 6 + kss;
            const int cur = ks & 1;
            if (ks < 23) {
                #pragma unroll
                for (int i = 0; i < 5; i++) Bf[cur ^ 1][i] = W0f[(ks + 1) * (W0_NT * 32) + i * 32];
            }
            uint32_t A[2][4];
            ldm_x4(A[0], aXb + kss * 32);
            ldm_x4(A[1], aXb + 16 * 208 + kss * 32);
            #pragma unroll
            for (int mt = 0; mt < 2; mt++)
                #pragma unroll
                for (int nt = 0; nt < 5; nt++)
                    mma_fp16_u2(acc0[mt][nt], A[mt], Bf[cur][nt]);
        }
        __syncthreads();   // next-X staged by all; current-X reads done
    }

    // epilogue 0 -> H0 (stride 336), packed celu
    #pragma unroll
    for (int mt = 0; mt < 2; mt++) {
        int row0 = mb + mt * 16 + (lane >> 2);
        #pragma unroll
        for (int nt = 0; nt < 5; nt++) {
            int col = nww * 40 + nt * 8 + 2 * (lane & 3);
            float* d = acc0[mt][nt];
            __half2 v01 = celu_h2(__floats2half2_rn(d[0] + sBias[col], d[1] + sBias[col + 1]));
            __half2 v23 = celu_h2(__floats2half2_rn(d[2] + sBias[col], d[3] + sBias[col + 1]));
            *(__half2*)(smem + H0_OFF + row0 * 336 + col * 2)       = v01;
            *(__half2*)(smem + H0_OFF + (row0 + 8) * 336 + col * 2) = v23;
        }
    }
    __syncthreads();

    // ===================== LAYER 1: 160 -> 128 (single pass, 4 n8 tiles/warp) =====================
    // warp nww owns n8 tiles {nww*2, nww*2+1, 8+nww*2, 9+nww*2}
    {
        float acc1[2][4][4];
        #pragma unroll
        for (int mt = 0; mt < 2; mt++)
            #pragma unroll
            for (int nt = 0; nt < 4; nt++)
                #pragma unroll
                for (int q = 0; q < 4; q++) acc1[mt][nt][q] = 0.f;

        const uint2* W1f = g_W1frag + ((size_t)t * W1_KS * W1_NT + nww * 2) * 32 + lane;
        const int toff[4] = {0, 32, 8 * 32, 9 * 32};
        uint2 Bf1[2][4];
        #pragma unroll
        for (int i = 0; i < 4; i++) Bf1[0][i] = W1f[toff[i]];

        const uint32_t aH0 = sb + H0_OFF + (mb + arow) * 336 + akb;
        #pragma unroll
        for (int ks = 0; ks < 10; ks++) {
            const int cur = ks & 1;
            if (ks < 9) {
                #pragma unroll
                for (int i = 0; i < 4; i++) Bf1[cur ^ 1][i] = W1f[(ks + 1) * (W1_NT * 32) + toff[i]];
            }
            uint32_t A[2][4];
            ldm_x4(A[0], aH0 + ks * 32);
            ldm_x4(A[1], aH0 + 16 * 336 + ks * 32);
            #pragma unroll
            for (int mt = 0; mt < 2; mt++)
                #pragma unroll
                for (int nt = 0; nt < 4; nt++)
                    mma_fp16_u2(acc1[mt][nt], A[mt], Bf1[cur][nt]);
        }

        // epilogue 1 -> H1 (stride 272), packed celu
        #pragma unroll
        for (int mt = 0; mt < 2; mt++) {
            int row0 = mb + mt * 16 + (lane >> 2);
            #pragma unroll
            for (int nt = 0; nt < 4; nt++) {
                int col = ((nt < 2) ? 0 : 64) + nww * 16 + (nt & 1) * 8 + 2 * (lane & 3);
                float* d = acc1[mt][nt];
                __half2 v01 = celu_h2(__floats2half2_rn(d[0] + sBias[160 + col], d[1] + sBias[160 + col + 1]));
                __half2 v23 = celu_h2(__floats2half2_rn(d[2] + sBias[160 + col], d[3] + sBias[160 + col + 1]));
                *(__half2*)(smem + H1_OFF + row0 * 272 + col * 2)       = v01;
                *(__half2*)(smem + H1_OFF + (row0 + 8) * 272 + col * 2) = v23;
            }
        }
    }
    __syncthreads();

    // ===================== LAYER 2: 128 -> 96 (+ fused layer 3 & reduce) =====================
    float acc2[2][3][4];
    #pragma unroll
    for (int mt = 0; mt < 2; mt++)
        #pragma unroll
        for (int nt = 0; nt < 3; nt++)
            #pragma unroll
            for (int q = 0; q < 4; q++) acc2[mt][nt][q] = 0.f;

    {
        const uint2* W2f = g_W2frag + ((size_t)t * W2_KS * W2_NT + nww * 3) * 32 + lane;
        uint2 Bf2[2][3];
        #pragma unroll
        for (int i = 0; i < 3; i++) Bf2[0][i] = W2f[i * 32];

        const uint32_t aH1 = sb + H1_OFF + (mb + arow) * 272 + akb;
        #pragma unroll
        for (int ks = 0; ks < 8; ks++) {
            const int cur = ks & 1;
            if (ks < 7) {
                #pragma unroll
                for (int i = 0; i < 3; i++) Bf2[cur ^ 1][i] = W2f[(ks + 1) * (W2_NT * 32) + i * 32];
            }
            uint32_t A[2][4];
            ldm_x4(A[0], aH1 + ks * 32);
            ldm_x4(A[1], aH1 + 16 * 272 + ks * 32);
            #pragma unroll
            for (int mt = 0; mt < 2; mt++)
                #pragma unroll
                for (int nt = 0; nt < 3; nt++)
                    mma_fp16_u2(acc2[mt][nt], A[mt], Bf2[cur][nt]);
        }
    }

    // layer-3 + molecule reduce: atomicAdd per-atom contribution into out_e
    {
        float part[2][2] = {{0.f, 0.f}, {0.f, 0.f}};
        #pragma unroll
        for (int mt = 0; mt < 2; mt++)
            #pragma unroll
            for (int nt = 0; nt < 3; nt++) {
                int col = nww * 24 + nt * 8 + 2 * (lane & 3);
                float* d = acc2[mt][nt];
                part[mt][0] += celu_f(d[0] + sBias[288 + col]) * sBias[384 + col]
                             + celu_f(d[1] + sBias[288 + col + 1]) * sBias[384 + col + 1];
                part[mt][1] += celu_f(d[2] + sBias[288 + col]) * sBias[384 + col]
                             + celu_f(d[3] + sBias[288 + col + 1]) * sBias[384 + col + 1];
            }
        #pragma unroll
        for (int mt = 0; mt < 2; mt++)
            #pragma unroll
            for (int h = 0; h < 2; h++) {
                part[mt][h] += __shfl_xor_sync(0xffffffffu, part[mt][h], 1);
                part[mt][h] += __shfl_xor_sync(0xffffffffu, part[mt][h], 2);
            }
        if ((lane & 3) == 0) {
            #pragma unroll
            for (int mt = 0; mt < 2; mt++)
                #pragma unroll
                for (int h = 0; h < 2; h++) {
                    int row = mb + mt * 16 + h * 8 + (lane >> 2);
                    int gi  = sIdx[row];
                    if (gi >= 0) {
                        float v = part[mt][h] + (nww == 0 ? sBias[480] : 0.f);
                        atomicAdd(out_e + (gi >> 6), v);
                    }
                }
        }
    }
}

extern "C" void kernel_launch(void* const* d_in, const int* in_sizes, int n_in,
                              void* d_out, int out_size)
{
    const int*   sp  = (const int*)d_in[0];
    const float* aev = (const float*)d_in[1];
    const float* W0 = (const float*)d_in[2];
    const float* b0 = (const float*)d_in[3];
    const float* W1 = (const float*)d_in[4];
    const float* b1 = (const float*)d_in[5];
    const float* W2 = (const float*)d_in[6];
    const float* b2 = (const float*)d_in[7];
    const float* W3 = (const float*)d_in[8];
    const float* b3 = (const float*)d_in[9];

    float* out = (float*)d_out;
    float* out_head;
    float* out_e;
    if (out_size == NB) { out_head = nullptr; out_e = out; }
    else                { out_head = out;     out_e = out + (out_size - NB); }

    k_detect    <<<1, 32>>>(sp);
    k_count_prep<<<CP_GRID, 256>>>(sp, W0, W1, W2);
    k_scatter   <<<NATOMS / 256, 256>>>(sp, out_head, out_e);

    cudaFuncSetAttribute(k_mlp_tc, cudaFuncAttributeMaxDynamicSharedMemorySize, SM_TOTAL);
    k_mlp_tc<<<MAXTILES, 256, SM_TOTAL>>>(aev, b0, b1, b2, W3, b3, out_e);
}

// round 13
// speedup vs baseline: 1.4267x; 1.4267x over previous
#include <cuda_runtime.h>
#include <cuda_fp16.h>
#include <cstdint>

// ---------------- problem constants ----------------
#define NB      2048
#define NA      64
#define NATOMS  (NB*NA)
#define AEV     384
#define N0      160
#define N1      128
#define N2      96
#define NTYPES  4
#define TILE    64
#define MAXTILES 2056

// ---------------- device scratch ----------------
__device__ int   g_is64;
__device__ int   g_counts[NTYPES];
__device__ int   g_cursor[NTYPES];
__device__ int   g_perm[NATOMS];

// fp16 weight chunk images, [n][k] layout, K=32 per chunk, row stride 80 B
__device__ uint4 g_W0img[NTYPES][12][800];   // 160 rows * 80 B
__device__ uint4 g_W1img[NTYPES][5][640];    // 128 rows * 80 B
__device__ uint4 g_W2img[NTYPES][4][480];    //  96 rows * 80 B

__device__ __forceinline__ float celu_f(float x) {
    return x > 0.f ? x : 0.1f * (__expf(10.f * x) - 1.f);
}
__device__ __forceinline__ __half2 celu_h2(__half2 x) {
    const __half2 ZERO  = __float2half2_rn(0.f);
    const __half2 ONE   = __float2half2_rn(1.f);
    const __half2 TEN   = __float2half2_rn(10.f);
    const __half2 TENTH = __float2half2_rn(0.1f);
    __half2 xa  = __hmin2(x, ZERO);
    __half2 ex  = h2exp(__hmul2(xa, TEN));
    __half2 neg = __hmul2(__hsub2(ex, ONE), TENTH);
    __half2 m   = __hgt2(x, ZERO);
    return __hfma2(m, __hsub2(x, neg), neg);
}
__device__ __forceinline__ int get_sp(const int* __restrict__ raw, int i, int is64) {
    return is64 ? raw[2 * i] : raw[i];
}
__device__ __forceinline__ uint32_t pack2h(float a, float b) {
    __half ha = __float2half_rn(a), hb = __float2half_rn(b);
    return (uint32_t)__half_as_ushort(ha) | ((uint32_t)__half_as_ushort(hb) << 16);
}
__device__ __forceinline__ uint32_t smem_u32(const void* p) {
    uint32_t a;
    asm("{ .reg .u64 t; cvta.to.shared.u64 t, %1; cvt.u32.u64 %0, t; }" : "=r"(a) : "l"(p));
    return a;
}
__device__ __forceinline__ void ldm_x4(uint32_t* r, uint32_t addr) {
    asm volatile("ldmatrix.sync.aligned.m8n8.x4.shared.b16 {%0,%1,%2,%3}, [%4];"
                 : "=r"(r[0]), "=r"(r[1]), "=r"(r[2]), "=r"(r[3]) : "r"(addr));
}
__device__ __forceinline__ void ldm_x2(uint32_t* r, uint32_t addr) {
    asm volatile("ldmatrix.sync.aligned.m8n8.x2.shared.b16 {%0,%1}, [%2];"
                 : "=r"(r[0]), "=r"(r[1]) : "r"(addr));
}
__device__ __forceinline__ void mma_fp16(float* d, const uint32_t* a, const uint32_t* b) {
    asm volatile(
        "mma.sync.aligned.m16n8k16.row.col.f32.f16.f16.f32 "
        "{%0,%1,%2,%3},{%4,%5,%6,%7},{%8,%9},{%0,%1,%2,%3};"
        : "+f"(d[0]), "+f"(d[1]), "+f"(d[2]), "+f"(d[3])
        : "r"(a[0]), "r"(a[1]), "r"(a[2]), "r"(a[3]), "r"(b[0]), "r"(b[1]));
}
__device__ __forceinline__ void cp16(uint32_t s, const void* g) {
    asm volatile("cp.async.cg.shared.global [%0], [%1], 16;" :: "r"(s), "l"(g) : "memory");
}
#define CP_COMMIT() asm volatile("cp.async.commit_group;" ::: "memory")
#define CP_WAIT(n)  asm volatile("cp.async.wait_group %0;" :: "n"(n) : "memory")

// ---------------- launch 1: dtype probe + reset ----------------
__global__ void k_detect(const int* __restrict__ sp_raw) {
    if (threadIdx.x == 0) {
        int odd_nonzero = 0;
        #pragma unroll
        for (int i = 1; i < 64; i += 2) odd_nonzero |= (sp_raw[i] != 0);
        g_is64 = odd_nonzero ? 0 : 1;
    }
    if (threadIdx.x < NTYPES) { g_counts[threadIdx.x] = 0; g_cursor[threadIdx.x] = 0; }
}

// ---------------- launch 2: count + weight prep (fused) ----------------
#define PREP_W0 122880   // 4t * 12c * 160n * 16j
#define PREP_W1 40960    // 4t * 5c * 128n * 16j
#define PREP_W2 24576    // 4t * 4c * 96n * 16j
#define PREP_TOTAL (PREP_W0 + PREP_W1 + PREP_W2)   // 188416
#define CP_GRID ((PREP_TOTAL + 255) / 256)

__global__ void k_count_prep(const int* __restrict__ sp,
                             const float* __restrict__ W0, const float* __restrict__ W1,
                             const float* __restrict__ W2) {
    int gid = blockIdx.x * blockDim.x + threadIdx.x;

    __shared__ int c[NTYPES];
    if (threadIdx.x < NTYPES) c[threadIdx.x] = 0;
    __syncthreads();
    if (gid < NATOMS) {
        int t = get_sp(sp, gid, g_is64);
        if ((unsigned)t < NTYPES) atomicAdd(&c[t], 1);
    }
    __syncthreads();
    if (threadIdx.x < NTYPES && c[threadIdx.x]) atomicAdd(&g_counts[threadIdx.x], c[threadIdx.x]);

    int idx = gid;
    if (idx < PREP_W0) {
        int t = idx / 30720, r = idx % 30720;
        int cc = r / 2560;  r %= 2560;
        int n = r / 16, j = r % 16;
        int kb = cc * 32 + 2 * j;
        uint32_t v = pack2h(W0[((size_t)t * AEV + kb)     * N0 + n],
                            W0[((size_t)t * AEV + kb + 1) * N0 + n]);
        *(uint32_t*)((char*)g_W0img[t][cc] + n * 80 + j * 4) = v;
    } else if (idx < PREP_W0 + PREP_W1) {
        int i2 = idx - PREP_W0;
        int t = i2 / 10240, r = i2 % 10240;
        int cc = r / 2048;  r %= 2048;
        int n = r / 16, j = r % 16;
        int kb = cc * 32 + 2 * j;
        uint32_t v = pack2h(W1[((size_t)t * N0 + kb)     * N1 + n],
                            W1[((size_t)t * N0 + kb + 1) * N1 + n]);
        *(uint32_t*)((char*)g_W1img[t][cc] + n * 80 + j * 4) = v;
    } else if (idx < PREP_TOTAL) {
        int i3 = idx - PREP_W0 - PREP_W1;
        int t = i3 / 6144, r = i3 % 6144;
        int cc = r / 1536;  r %= 1536;
        int n = r / 16, j = r % 16;
        int kb = cc * 32 + 2 * j;
        uint32_t v = pack2h(W2[((size_t)t * N1 + kb)     * N2 + n],
                            W2[((size_t)t * N1 + kb + 1) * N2 + n]);
        *(uint32_t*)((char*)g_W2img[t][cc] + n * 80 + j * 4) = v;
    }
}

// ---------------- launch 3: scatter + output-head + out_e zero ----------------
__global__ void k_scatter(const int* __restrict__ sp,
                          float* __restrict__ out_head,
                          float* __restrict__ out_e) {
    __shared__ int soff[NTYPES];
    __shared__ int base[NTYPES];
    __shared__ int lc[NTYPES];
    if (threadIdx.x == 0) {
        int o = 0;
        #pragma unroll
        for (int t = 0; t < NTYPES; t++) { soff[t] = o; o += g_counts[t]; }
    }
    if (threadIdx.x < NTYPES) lc[threadIdx.x] = 0;
    __syncthreads();
    int i = blockIdx.x * blockDim.x + threadIdx.x;
    if (i < NB) out_e[i] = 0.f;
    int t = -1, r = 0;
    if (i < NATOMS) {
        int tv = get_sp(sp, i, g_is64);
        if (out_head) out_head[i] = (float)tv;
        if ((unsigned)tv < NTYPES) { t = tv; r = atomicAdd(&lc[t], 1); }
    }
    __syncthreads();
    if (threadIdx.x < NTYPES)
        base[threadIdx.x] = lc[threadIdx.x] ? atomicAdd(&g_cursor[threadIdx.x], lc[threadIdx.x]) : 0;
    __syncthreads();
    if (t >= 0) g_perm[soff[t] + base[t] + r] = i;
}

// ---------------- launch 4: fused MLP (K=32 chunked, double-buffered WB) ----------------
// SMEM (bytes): BIAS 0..1936 | SIDX 1936..2192 | WB[2] @2560 (2x12800=25600)
//               X @28160 (13312; H1 17408 overlays) | H0 @45568 (21504)  -> total 67072
#define BIAS_OFF 0
#define SIDX_OFF 1936
#define WB_OFF   2560
#define WBUF_SZ  12800
#define X_OFF    28160
#define H1_OFF   28160
#define H0_OFF   45568
#define SM_TOTAL 67072

__global__ __launch_bounds__(256, 3)
void k_mlp_tc(const float* __restrict__ aev,
              const float* __restrict__ b0, const float* __restrict__ b1,
              const float* __restrict__ b2, const float* __restrict__ W3,
              const float* __restrict__ b3,
              float* __restrict__ out_e)
{
    // derive this CTA's tile (type, start, len) from g_counts
    int t = -1, gstart = 0, len = 0;
    {
        int rem = blockIdx.x, off = 0;
        #pragma unroll
        for (int tt = 0; tt < NTYPES; tt++) {
            int cc = g_counts[tt];
            int ntl = (cc + TILE - 1) / TILE;
            if (t < 0) {
                if (rem < ntl) {
                    t = tt;
                    gstart = off + rem * TILE;
                    int l = cc - rem * TILE;
                    len = l < TILE ? l : TILE;
                } else rem -= ntl;
            }
            off += cc;
        }
    }
    if (t < 0) return;

    extern __shared__ char smem[];
    const uint32_t sb = smem_u32(smem);
    float* sBias = (float*)(smem + BIAS_OFF);
    int*   sIdx  = (int*)(smem + SIDX_OFF);

    const int tid  = threadIdx.x;
    const int lane = tid & 31;
    const int w    = tid >> 5;
    const int mw   = w & 1;         // M group (0/1)
    const int nww  = w >> 1;        // N group (0..3)
    const int mb   = mw * 32;

    if (tid < TILE) sIdx[tid] = (tid < len) ? g_perm[gstart + tid] : -1;
    for (int i = tid; i < N0; i += 256) sBias[i] = b0[t * N0 + i];
    for (int i = tid; i < N1; i += 256) sBias[160 + i] = b1[t * N1 + i];
    for (int i = tid; i < N2; i += 256) { sBias[288 + i] = b2[t * N2 + i]; sBias[384 + i] = W3[t * N2 + i]; }
    if (tid == 0) sBias[480] = b3[t];

    // prefetch W0 chunk 0 into WB0
    {
        const uint4* src = g_W0img[t][0];
        for (int i = tid; i < 800; i += 256) cp16(sb + WB_OFF + i * 16, src + i);
        CP_COMMIT();
    }
    __syncthreads();   // sIdx/bias visible

    // X staging params (one 96-k chunk, 64 rows x 208 B)
    const int srow  = tid >> 2;
    const int scol0 = (tid & 3) * 24;
    const int sgi   = sIdx[srow];
    // stage X chunk 0
    {
        const float4* src = (const float4*)(aev + (size_t)(sgi < 0 ? 0 : sgi) * AEV + scol0);
        char* dx = smem + X_OFF + srow * 208 + scol0 * 2;
        #pragma unroll
        for (int i = 0; i < 6; i++) {
            float4 v = (sgi >= 0) ? src[i] : make_float4(0.f, 0.f, 0.f, 0.f);
            *(__half2*)(dx + i * 8)     = __floats2half2_rn(v.x, v.y);
            *(__half2*)(dx + i * 8 + 4) = __floats2half2_rn(v.z, v.w);
        }
    }

    // lane offsets for ldmatrix
    const int arow  = (lane & 7) + (lane & 8);
    const int akb   = (lane & 16) ? 16 : 0;
    const int brow  = (lane & 7) + ((lane & 16) ? 8 : 0);
    const int bkb   = (lane & 8) ? 16 : 0;
    const int brow2 = (lane & 7);
    const int bkb2  = (lane & 8) ? 16 : 0;

    const uint32_t aXbase = sb + X_OFF + (mb + arow) * 208 + akb;

    // ===================== LAYER 0: 384 -> 160 (12 chunks of K=32) =====================
    float acc0[2][5][4];
    #pragma unroll
    for (int mt = 0; mt < 2; mt++)
        #pragma unroll
        for (int nt = 0; nt < 5; nt++)
            #pragma unroll
            for (int q = 0; q < 4; q++) acc0[mt][nt][q] = 0.f;

    #pragma unroll 1
    for (int c = 0; c < 12; c++) {
        CP_WAIT(0);        // own copies for chunk c done
        __syncthreads();   // all threads' chunk-c copies visible; chunk c-1 MMAs retired (WAR)
        if (c < 11) {      // prefetch chunk c+1 (overlaps this chunk's MMAs)
            const uint4* src = g_W0img[t][c + 1];
            uint32_t dst = sb + WB_OFF + ((c + 1) & 1) * WBUF_SZ;
            for (int i = tid; i < 800; i += 256) cp16(dst + i * 16, src + i);
            CP_COMMIT();
        }
        if (c > 0 && (c % 3) == 0) {   // restage X for chunks c..c+2
            const float4* src = (const float4*)(aev + (size_t)(sgi < 0 ? 0 : sgi) * AEV + (c / 3) * 96 + scol0);
            char* dx = smem + X_OFF + srow * 208 + scol0 * 2;
            #pragma unroll
            for (int i = 0; i < 6; i++) {
                float4 v = (sgi >= 0) ? src[i] : make_float4(0.f, 0.f, 0.f, 0.f);
                *(__half2*)(dx + i * 8)     = __floats2half2_rn(v.x, v.y);
                *(__half2*)(dx + i * 8 + 4) = __floats2half2_rn(v.z, v.w);
            }
            __syncthreads();           // new X visible to all
        }

        const uint32_t wb  = sb + WB_OFF + (c & 1) * WBUF_SZ;
        const uint32_t bA0 = wb + (nww * 40 + brow) * 80 + bkb;
        const uint32_t bB0 = bA0 + 16 * 80;
        const uint32_t bC0 = wb + (nww * 40 + 32 + brow2) * 80 + bkb2;
        const uint32_t aC  = aXbase + (c % 3) * 64;

        #pragma unroll
        for (int ks2 = 0; ks2 < 2; ks2++) {
            const uint32_t kb = ks2 * 32;
            uint32_t A[2][4], B0[4], B1[4], B2[2];
            ldm_x4(A[0], aC + kb);
            ldm_x4(A[1], aC + 16 * 208 + kb);
            ldm_x4(B0, bA0 + kb);
            ldm_x4(B1, bB0 + kb);
            ldm_x2(B2, bC0 + kb);
            #pragma unroll
            for (int mt = 0; mt < 2; mt++) {
                mma_fp16(acc0[mt][0], A[mt], B0);
                mma_fp16(acc0[mt][1], A[mt], B0 + 2);
                mma_fp16(acc0[mt][2], A[mt], B1);
                mma_fp16(acc0[mt][3], A[mt], B1 + 2);
                mma_fp16(acc0[mt][4], A[mt], B2);
            }
        }
    }
    __syncthreads();   // all L0 MMAs done; WB + X free

    // prefetch W1 chunk 0 (overlaps epilogue 0)
    {
        const uint4* src = g_W1img[t][0];
        for (int i = tid; i < 640; i += 256) cp16(sb + WB_OFF + i * 16, src + i);
        CP_COMMIT();
    }

    // epilogue 0 -> H0 (stride 336), packed celu
    #pragma unroll
    for (int mt = 0; mt < 2; mt++) {
        int row0 = mb + mt * 16 + (lane >> 2);
        #pragma unroll
        for (int nt = 0; nt < 5; nt++) {
            int col = nww * 40 + nt * 8 + 2 * (lane & 3);
            float* d = acc0[mt][nt];
            __half2 v01 = celu_h2(__floats2half2_rn(d[0] + sBias[col], d[1] + sBias[col + 1]));
            __half2 v23 = celu_h2(__floats2half2_rn(d[2] + sBias[col], d[3] + sBias[col + 1]));
            *(__half2*)(smem + H0_OFF + row0 * 336 + col * 2)       = v01;
            *(__half2*)(smem + H0_OFF + (row0 + 8) * 336 + col * 2) = v23;
        }
    }
    __syncthreads();   // H0 visible

    // ===================== LAYER 1: 160 -> 128 (5 chunks of K=32, single N pass) =====================
    float acc1[2][4][4];
    #pragma unroll
    for (int mt = 0; mt < 2; mt++)
        #pragma unroll
        for (int nt = 0; nt < 4; nt++)
            #pragma unroll
            for (int q = 0; q < 4; q++) acc1[mt][nt][q] = 0.f;

    const uint32_t aH0 = sb + H0_OFF + (mb + arow) * 336 + akb;

    #pragma unroll 1
    for (int c = 0; c < 5; c++) {
        CP_WAIT(0);
        __syncthreads();   // chunk-c copies visible; chunk c-1 MMAs retired
        if (c < 4) {
            const uint4* src = g_W1img[t][c + 1];
            uint32_t dst = sb + WB_OFF + ((c + 1) & 1) * WBUF_SZ;
            for (int i = tid; i < 640; i += 256) cp16(dst + i * 16, src + i);
            CP_COMMIT();
        }
        const uint32_t wb  = sb + WB_OFF + (c & 1) * WBUF_SZ;
        const uint32_t bA1 = wb + (nww * 32 + brow) * 80 + bkb;
        const uint32_t bB1 = bA1 + 16 * 80;

        #pragma unroll
        for (int ks2 = 0; ks2 < 2; ks2++) {
            const int ks = c * 2 + ks2;
            uint32_t A[2][4], B0[4], B1[4];
            ldm_x4(A[0], aH0 + ks * 32);
            ldm_x4(A[1], aH0 + 16 * 336 + ks * 32);
            ldm_x4(B0, bA1 + ks2 * 32);
            ldm_x4(B1, bB1 + ks2 * 32);
            #pragma unroll
            for (int mt = 0; mt < 2; mt++) {
                mma_fp16(acc1[mt][0], A[mt], B0);
                mma_fp16(acc1[mt][1], A[mt], B0 + 2);
                mma_fp16(acc1[mt][2], A[mt], B1);
                mma_fp16(acc1[mt][3], A[mt], B1 + 2);
            }
        }
    }
    __syncthreads();   // all L1 MMAs done; WB free

    // prefetch W2 chunk 0 (overlaps epilogue 1)
    {
        const uint4* src = g_W2img[t][0];
        for (int i = tid; i < 480; i += 256) cp16(sb + WB_OFF + i * 16, src + i);
        CP_COMMIT();
    }

    // epilogue 1 -> H1 (stride 272), packed celu
    #pragma unroll
    for (int mt = 0; mt < 2; mt++) {
        int row0 = mb + mt * 16 + (lane >> 2);
        #pragma unroll
        for (int nt = 0; nt < 4; nt++) {
            int col = nww * 32 + nt * 8 + 2 * (lane & 3);
            float* d = acc1[mt][nt];
            __half2 v01 = celu_h2(__floats2half2_rn(d[0] + sBias[160 + col], d[1] + sBias[160 + col + 1]));
            __half2 v23 = celu_h2(__floats2half2_rn(d[2] + sBias[160 + col], d[3] + sBias[160 + col + 1]));
            *(__half2*)(smem + H1_OFF + row0 * 272 + col * 2)       = v01;
            *(__half2*)(smem + H1_OFF + (row0 + 8) * 272 + col * 2) = v23;
        }
    }
    __syncthreads();   // H1 visible

    // ===================== LAYER 2: 128 -> 96 (4 chunks of K=32) =====================
    float acc2[2][3][4];
    #pragma unroll
    for (int mt = 0; mt < 2; mt++)
        #pragma unroll
        for (int nt = 0; nt < 3; nt++)
            #pragma unroll
            for (int q = 0; q < 4; q++) acc2[mt][nt][q] = 0.f;

    const uint32_t aH1 = sb + H1_OFF + (mb + arow) * 272 + akb;

    #pragma unroll 1
    for (int c = 0; c < 4; c++) {
        CP_WAIT(0);
        __syncthreads();   // chunk-c copies visible; chunk c-1 MMAs retired
        if (c < 3) {
            const uint4* src = g_W2img[t][c + 1];
            uint32_t dst = sb + WB_OFF + ((c + 1) & 1) * WBUF_SZ;
            for (int i = tid; i < 480; i += 256) cp16(dst + i * 16, src + i);
            CP_COMMIT();
        }
        const uint32_t wb  = sb + WB_OFF + (c & 1) * WBUF_SZ;
        const uint32_t bA2 = wb + (nww * 24 + brow) * 80 + bkb;
        const uint32_t bC2 = wb + (nww * 24 + 16 + brow2) * 80 + bkb2;

        #pragma unroll
        for (int ks2 = 0; ks2 < 2; ks2++) {
            const int ks = c * 2 + ks2;
            uint32_t A[2][4], B0[4], B2[2];
            ldm_x4(A[0], aH1 + ks * 32);
            ldm_x4(A[1], aH1 + 16 * 272 + ks * 32);
            ldm_x4(B0, bA2 + ks2 * 32);
            ldm_x2(B2, bC2 + ks2 * 32);
            #pragma unroll
            for (int mt = 0; mt < 2; mt++) {
                mma_fp16(acc2[mt][0], A[mt], B0);
                mma_fp16(acc2[mt][1], A[mt], B0 + 2);
                mma_fp16(acc2[mt][2], A[mt], B2);
            }
        }
    }

    // layer-3 + molecule reduce: atomicAdd per-atom contribution into out_e
    {
        float part[2][2] = {{0.f, 0.f}, {0.f, 0.f}};
        #pragma unroll
        for (int mt = 0; mt < 2; mt++)
            #pragma unroll
            for (int nt = 0; nt < 3; nt++) {
                int col = nww * 24 + nt * 8 + 2 * (lane & 3);
                float* d = acc2[mt][nt];
                part[mt][0] += celu_f(d[0] + sBias[288 + col]) * sBias[384 + col]
                             + celu_f(d[1] + sBias[288 + col + 1]) * sBias[384 + col + 1];
                part[mt][1] += celu_f(d[2] + sBias[288 + col]) * sBias[384 + col]
                             + celu_f(d[3] + sBias[288 + col + 1]) * sBias[384 + col + 1];
            }
        #pragma unroll
        for (int mt = 0; mt < 2; mt++)
            #pragma unroll
            for (int h = 0; h < 2; h++) {
                part[mt][h] += __shfl_xor_sync(0xffffffffu, part[mt][h], 1);
                part[mt][h] += __shfl_xor_sync(0xffffffffu, part[mt][h], 2);
            }
        if ((lane & 3) == 0) {
            #pragma unroll
            for (int mt = 0; mt < 2; mt++)
                #pragma unroll
                for (int h = 0; h < 2; h++) {
                    int row = mb + mt * 16 + h * 8 + (lane >> 2);
                    int gi  = sIdx[row];
                    if (gi >= 0) {
                        float v = part[mt][h] + (nww == 0 ? sBias[480] : 0.f);
                        atomicAdd(out_e + (gi >> 6), v);
                    }
                }
        }
    }
}

extern "C" void kernel_launch(void* const* d_in, const int* in_sizes, int n_in,
                              void* d_out, int out_size)
{
    const int*   sp  = (const int*)d_in[0];
    const float* aev = (const float*)d_in[1];
    const float* W0 = (const float*)d_in[2];
    const float* b0 = (const float*)d_in[3];
    const float* W1 = (const float*)d_in[4];
    const float* b1 = (const float*)d_in[5];
    const float* W2 = (const float*)d_in[6];
    const float* b2 = (const float*)d_in[7];
    const float* W3 = (const float*)d_in[8];
    const float* b3 = (const float*)d_in[9];

    float* out = (float*)d_out;
    float* out_head;
    float* out_e;
    if (out_size == NB) { out_head = nullptr; out_e = out; }
    else                { out_head = out;     out_e = out + (out_size - NB); }

    k_detect    <<<1, 32>>>(sp);
    k_count_prep<<<CP_GRID, 256>>>(sp, W0, W1, W2);
    k_scatter   <<<NATOMS / 256, 256>>>(sp, out_head, out_e);

    cudaFuncSetAttribute(k_mlp_tc, cudaFuncAttributeMaxDynamicSharedMemorySize, SM_TOTAL);
    k_mlp_tc<<<MAXTILES, 256, SM_TOTAL>>>(aev, b0, b1, b2, W3, b3, out_e);
}

// round 14
// speedup vs baseline: 1.5825x; 1.1092x over previous
#include <cuda_runtime.h>
#include <cuda_fp16.h>
#include <cstdint>

// ---------------- problem constants ----------------
#define NB      2048
#define NA      64
#define NATOMS  (NB*NA)
#define AEV     384
#define N0      160
#define N1      128
#define N2      96
#define NTYPES  4
#define TILE    64
#define MAXTILES 2056

// ---------------- device scratch ----------------
__device__ int   g_is64;
__device__ int   g_counts[NTYPES];
__device__ int   g_cursor[NTYPES];
__device__ int   g_perm[NATOMS];

// fp16 weight images, [n][k] layout, padded strides (bytes): W0 208, W1 336, W2 272
__device__ uint4 g_W0img[NTYPES][4][2080];   // per 96-K chunk: 160*208 B
__device__ uint4 g_W1img[NTYPES][2][1344];   // per 64-N half:  64*336 B (K=160)
__device__ uint4 g_W2img[NTYPES][1632];      // 96*272 B (K=128)

__device__ __forceinline__ float celu_f(float x) {
    return x > 0.f ? x : 0.1f * (__expf(10.f * x) - 1.f);
}
__device__ __forceinline__ __half2 celu_h2(__half2 x) {
    const __half2 ZERO  = __float2half2_rn(0.f);
    const __half2 ONE   = __float2half2_rn(1.f);
    const __half2 TEN   = __float2half2_rn(10.f);
    const __half2 TENTH = __float2half2_rn(0.1f);
    __half2 xa  = __hmin2(x, ZERO);
    __half2 ex  = h2exp(__hmul2(xa, TEN));
    __half2 neg = __hmul2(__hsub2(ex, ONE), TENTH);
    __half2 m   = __hgt2(x, ZERO);
    return __hfma2(m, __hsub2(x, neg), neg);
}
__device__ __forceinline__ int get_sp(const int* __restrict__ raw, int i, int is64) {
    return is64 ? raw[2 * i] : raw[i];
}
__device__ __forceinline__ uint32_t pack2h(float a, float b) {
    __half ha = __float2half_rn(a), hb = __float2half_rn(b);
    return (uint32_t)__half_as_ushort(ha) | ((uint32_t)__half_as_ushort(hb) << 16);
}
__device__ __forceinline__ uint32_t smem_u32(const void* p) {
    uint32_t a;
    asm("{ .reg .u64 t; cvta.to.shared.u64 t, %1; cvt.u32.u64 %0, t; }" : "=r"(a) : "l"(p));
    return a;
}
__device__ __forceinline__ void ldm_x4(uint32_t* r, uint32_t addr) {
    asm volatile("ldmatrix.sync.aligned.m8n8.x4.shared.b16 {%0,%1,%2,%3}, [%4];"
                 : "=r"(r[0]), "=r"(r[1]), "=r"(r[2]), "=r"(r[3]) : "r"(addr));
}
__device__ __forceinline__ void ldm_x2(uint32_t* r, uint32_t addr) {
    asm volatile("ldmatrix.sync.aligned.m8n8.x2.shared.b16 {%0,%1}, [%2];"
                 : "=r"(r[0]), "=r"(r[1]) : "r"(addr));
}
__device__ __forceinline__ void mma_fp16(float* d, const uint32_t* a, const uint32_t* b) {
    asm volatile(
        "mma.sync.aligned.m16n8k16.row.col.f32.f16.f16.f32 "
        "{%0,%1,%2,%3},{%4,%5,%6,%7},{%8,%9},{%0,%1,%2,%3};"
        : "+f"(d[0]), "+f"(d[1]), "+f"(d[2]), "+f"(d[3])
        : "r"(a[0]), "r"(a[1]), "r"(a[2]), "r"(a[3]), "r"(b[0]), "r"(b[1]));
}
__device__ __forceinline__ void cp16(uint32_t s, const void* g) {
    asm volatile("cp.async.cg.shared.global [%0], [%1], 16;" :: "r"(s), "l"(g) : "memory");
}
#define CP_COMMIT() asm volatile("cp.async.commit_group;" ::: "memory")
#define CP_WAIT(n)  asm volatile("cp.async.wait_group %0;" :: "n"(n) : "memory")

// ---------------- launch 1: dtype probe + reset ----------------
__global__ void k_detect(const int* __restrict__ sp_raw) {
    if (threadIdx.x == 0) {
        int odd_nonzero = 0;
        #pragma unroll
        for (int i = 1; i < 64; i += 2) odd_nonzero |= (sp_raw[i] != 0);
        g_is64 = odd_nonzero ? 0 : 1;
    }
    if (threadIdx.x < NTYPES) { g_counts[threadIdx.x] = 0; g_cursor[threadIdx.x] = 0; }
}

// ---------------- launch 2: count + weight prep (fused) ----------------
#define PREP_W0 122880   // 4t * 4c * 160n * 48j
#define PREP_W1 40960    // 4t * 2h * 64n * 80j
#define PREP_W2 24576    // 4t * 96n * 64j
#define PREP_TOTAL (PREP_W0 + PREP_W1 + PREP_W2)
#define CP_GRID ((PREP_TOTAL + 255) / 256)

__global__ void k_count_prep(const int* __restrict__ sp,
                             const float* __restrict__ W0, const float* __restrict__ W1,
                             const float* __restrict__ W2) {
    int gid = blockIdx.x * blockDim.x + threadIdx.x;

    __shared__ int c[NTYPES];
    if (threadIdx.x < NTYPES) c[threadIdx.x] = 0;
    __syncthreads();
    if (gid < NATOMS) {
        int t = get_sp(sp, gid, g_is64);
        if ((unsigned)t < NTYPES) atomicAdd(&c[t], 1);
    }
    __syncthreads();
    if (threadIdx.x < NTYPES && c[threadIdx.x]) atomicAdd(&g_counts[threadIdx.x], c[threadIdx.x]);

    int idx = gid;
    if (idx < PREP_W0) {
        int t = idx / 30720, r = idx % 30720;
        int cc = r / 7680;  r %= 7680;
        int n = r / 48, j = r % 48;
        int k0 = cc * 96 + 2 * j;
        float v0 = W0[((size_t)t * AEV + k0)     * N0 + n];
        float v1 = W0[((size_t)t * AEV + k0 + 1) * N0 + n];
        *(uint32_t*)((char*)g_W0img[t][cc] + n * 208 + j * 4) = pack2h(v0, v1);
    } else if (idx < PREP_W0 + PREP_W1) {
        int i2 = idx - PREP_W0;
        int t = i2 / 10240, r = i2 % 10240;
        int h = r / 5120;  r %= 5120;
        int n = r / 80, j = r % 80;
        int k0 = 2 * j;
        float v0 = W1[((size_t)t * N0 + k0)     * N1 + h * 64 + n];
        float v1 = W1[((size_t)t * N0 + k0 + 1) * N1 + h * 64 + n];
        *(uint32_t*)((char*)g_W1img[t][h] + n * 336 + j * 4) = pack2h(v0, v1);
    } else if (idx < PREP_TOTAL) {
        int i3 = idx - PREP_W0 - PREP_W1;
        int t = i3 / 6144, r = i3 % 6144;
        int n = r / 64, j = r % 64;
        int k0 = 2 * j;
        float v0 = W2[((size_t)t * N1 + k0)     * N2 + n];
        float v1 = W2[((size_t)t * N1 + k0 + 1) * N2 + n];
        *(uint32_t*)((char*)g_W2img[t] + n * 272 + j * 4) = pack2h(v0, v1);
    }
}

// ---------------- launch 3: scatter + output-head + out_e zero ----------------
__global__ void k_scatter(const int* __restrict__ sp,
                          float* __restrict__ out_head,
                          float* __restrict__ out_e) {
    __shared__ int soff[NTYPES];
    __shared__ int base[NTYPES];
    __shared__ int lc[NTYPES];
    if (threadIdx.x == 0) {
        int o = 0;
        #pragma unroll
        for (int t = 0; t < NTYPES; t++) { soff[t] = o; o += g_counts[t]; }
    }
    if (threadIdx.x < NTYPES) lc[threadIdx.x] = 0;
    __syncthreads();
    int i = blockIdx.x * blockDim.x + threadIdx.x;
    if (i < NB) out_e[i] = 0.f;
    int t = -1, r = 0;
    if (i < NATOMS) {
        int tv = get_sp(sp, i, g_is64);
        if (out_head) out_head[i] = (float)tv;
        if ((unsigned)tv < NTYPES) { t = tv; r = atomicAdd(&lc[t], 1); }
    }
    __syncthreads();
    if (threadIdx.x < NTYPES)
        base[threadIdx.x] = lc[threadIdx.x] ? atomicAdd(&g_cursor[threadIdx.x], lc[threadIdx.x]) : 0;
    __syncthreads();
    if (t >= 0) g_perm[soff[t] + base[t] + r] = i;
}

// ---------------- launch 4: fused MLP (64-atom tiles, 2Mx4N warps, A-pipelined) ----------------
#define BIAS_OFF 0
#define SIDX_OFF 1936
#define WB_OFF   2560
#define X_OFF    35840
#define H1_OFF   35840
#define H0_OFF   53248
#define SM_TOTAL 74752

__global__ __launch_bounds__(256, 3)
void k_mlp_tc(const float* __restrict__ aev,
              const float* __restrict__ b0, const float* __restrict__ b1,
              const float* __restrict__ b2, const float* __restrict__ W3,
              const float* __restrict__ b3,
              float* __restrict__ out_e)
{
    // derive this CTA's tile (type, start, len) from g_counts
    int t = -1, gstart = 0, len = 0;
    {
        int rem = blockIdx.x, off = 0;
        #pragma unroll
        for (int tt = 0; tt < NTYPES; tt++) {
            int cc = g_counts[tt];
            int ntl = (cc + TILE - 1) / TILE;
            if (t < 0) {
                if (rem < ntl) {
                    t = tt;
                    gstart = off + rem * TILE;
                    int l = cc - rem * TILE;
                    len = l < TILE ? l : TILE;
                } else rem -= ntl;
            }
            off += cc;
        }
    }
    if (t < 0) return;

    extern __shared__ char smem[];
    const uint32_t sb = smem_u32(smem);
    float* sBias = (float*)(smem + BIAS_OFF);
    int*   sIdx  = (int*)(smem + SIDX_OFF);

    const int tid  = threadIdx.x;
    const int lane = tid & 31;
    const int w    = tid >> 5;
    const int mw   = w & 1;         // M group (0/1)
    const int nww  = w >> 1;        // N group (0..3)
    const int mb   = mw * 32;

    if (tid < TILE) sIdx[tid] = (tid < len) ? g_perm[gstart + tid] : -1;
    for (int i = tid; i < N0; i += 256) sBias[i] = b0[t * N0 + i];
    for (int i = tid; i < N1; i += 256) sBias[160 + i] = b1[t * N1 + i];
    for (int i = tid; i < N2; i += 256) { sBias[288 + i] = b2[t * N2 + i]; sBias[384 + i] = W3[t * N2 + i]; }
    if (tid == 0) sBias[480] = b3[t];

    // prefetch W0 chunk 0
    {
        const uint4* src = g_W0img[t][0];
        for (int i = tid; i < 2080; i += 256) cp16(sb + WB_OFF + i * 16, src + i);
        CP_COMMIT();
    }
    __syncthreads();

    // lane offsets for ldmatrix
    const int arow  = (lane & 7) + (lane & 8);
    const int akb   = (lane & 16) ? 16 : 0;
    const int brow  = (lane & 7) + ((lane & 16) ? 8 : 0);
    const int bkb   = (lane & 8) ? 16 : 0;
    const int brow2 = (lane & 7);               // x2 B (n8k16)
    const int bkb2  = (lane & 8) ? 16 : 0;

    // ===================== LAYER 0: 384 -> 160 =====================
    float acc0[2][5][4];
    #pragma unroll
    for (int mt = 0; mt < 2; mt++)
        #pragma unroll
        for (int nt = 0; nt < 5; nt++)
            #pragma unroll
            for (int q = 0; q < 4; q++) acc0[mt][nt][q] = 0.f;

    const uint32_t aX  = sb + X_OFF + (mb + arow) * 208 + akb;
    const uint32_t bA0 = sb + WB_OFF + (nww * 40 + brow) * 208 + bkb;           // n16 @ +0
    const uint32_t bB0 = bA0 + 16 * 208;                                         // n16 @ +16
    const uint32_t bC0 = sb + WB_OFF + (nww * 40 + 32 + brow2) * 208 + bkb2;     // n8  @ +32

    const int srow  = tid >> 2;
    const int scol0 = (tid & 3) * 24;
    const int sgi   = sIdx[0];   // placeholder; real value read below after barrier semantics
    (void)sgi;

    for (int c = 0; c < 4; c++) {
        // stage X chunk c: row = tid/4 (0..63), 24 cols per quarter-thread
        {
            int gi = sIdx[srow];
            const float4* src = (const float4*)(aev + (size_t)(gi < 0 ? 0 : gi) * AEV + c * 96 + scol0);
            char* dx = smem + X_OFF + srow * 208 + scol0 * 2;
            #pragma unroll
            for (int i = 0; i < 6; i++) {
                float4 v = (gi >= 0) ? src[i] : make_float4(0.f, 0.f, 0.f, 0.f);
                *(__half2*)(dx + i * 8)     = __floats2half2_rn(v.x, v.y);
                *(__half2*)(dx + i * 8 + 4) = __floats2half2_rn(v.z, v.w);
            }
        }
        CP_WAIT(0);
        __syncthreads();          // W0 chunk + X ready

        uint32_t Ab[2][2][4];
        ldm_x4(Ab[0][0], aX);
        ldm_x4(Ab[0][1], aX + 16 * 208);
        #pragma unroll
        for (int ks = 0; ks < 6; ks++) {
            const uint32_t kb = ks * 32;
            const int cur = ks & 1;
            uint32_t B0[4], B1[4], B2[2];
            ldm_x4(B0, bA0 + kb);
            ldm_x4(B1, bB0 + kb);
            ldm_x2(B2, bC0 + kb);
            if (ks < 5) {         // prefetch A for next ks
                ldm_x4(Ab[cur ^ 1][0], aX + kb + 32);
                ldm_x4(Ab[cur ^ 1][1], aX + 16 * 208 + kb + 32);
            }
            #pragma unroll
            for (int mt = 0; mt < 2; mt++) {
                mma_fp16(acc0[mt][0], Ab[cur][mt], B0);
                mma_fp16(acc0[mt][1], Ab[cur][mt], B0 + 2);
                mma_fp16(acc0[mt][2], Ab[cur][mt], B1);
                mma_fp16(acc0[mt][3], Ab[cur][mt], B1 + 2);
                mma_fp16(acc0[mt][4], Ab[cur][mt], B2);
            }
        }
        __syncthreads();          // all reads of X/WB done before overwrite

        if (c < 3) {
            const uint4* src = g_W0img[t][c + 1];
            for (int i = tid; i < 2080; i += 256) cp16(sb + WB_OFF + i * 16, src + i);
            CP_COMMIT();
        }
    }

    // prefetch W1 half 0 into WB (overlaps epilogue 0)
    {
        const uint4* src = g_W1img[t][0];
        for (int i = tid; i < 1344; i += 256) cp16(sb + WB_OFF + i * 16, src + i);
        CP_COMMIT();
    }

    // epilogue 0 -> H0 (stride 336), packed celu
    #pragma unroll
    for (int mt = 0; mt < 2; mt++) {
        int row0 = mb + mt * 16 + (lane >> 2);
        #pragma unroll
        for (int nt = 0; nt < 5; nt++) {
            int col = nww * 40 + nt * 8 + 2 * (lane & 3);
            float* d = acc0[mt][nt];
            __half2 v01 = celu_h2(__floats2half2_rn(d[0] + sBias[col], d[1] + sBias[col + 1]));
            __half2 v23 = celu_h2(__floats2half2_rn(d[2] + sBias[col], d[3] + sBias[col + 1]));
            *(__half2*)(smem + H0_OFF + row0 * 336 + col * 2)       = v01;
            *(__half2*)(smem + H0_OFF + (row0 + 8) * 336 + col * 2) = v23;
        }
    }
    CP_WAIT(0);
    __syncthreads();

    // ===================== LAYER 1: 160 -> 128 (two 64-N halves) =====================
    const uint32_t aH0 = sb + H0_OFF + (mb + arow) * 336 + akb;
    const uint32_t bW1 = sb + WB_OFF + (nww * 16 + brow) * 336 + bkb;   // n16 per warp per half

    for (int half = 0; half < 2; half++) {
        float acc1[2][2][4];
        #pragma unroll
        for (int mt = 0; mt < 2; mt++)
            #pragma unroll
            for (int nt = 0; nt < 2; nt++)
                #pragma unroll
                for (int q = 0; q < 4; q++) acc1[mt][nt][q] = 0.f;

        uint32_t Ab[2][2][4], Bb[2][4];
        ldm_x4(Ab[0][0], aH0);
        ldm_x4(Ab[0][1], aH0 + 16 * 336);
        ldm_x4(Bb[0], bW1);
        #pragma unroll
        for (int ks = 0; ks < 10; ks++) {
            const int cur = ks & 1;
            if (ks < 9) {
                const uint32_t kb2 = (ks + 1) * 32;
                ldm_x4(Ab[cur ^ 1][0], aH0 + kb2);
                ldm_x4(Ab[cur ^ 1][1], aH0 + 16 * 336 + kb2);
                ldm_x4(Bb[cur ^ 1], bW1 + kb2);
            }
            #pragma unroll
            for (int mt = 0; mt < 2; mt++) {
                mma_fp16(acc1[mt][0], Ab[cur][mt], Bb[cur]);
                mma_fp16(acc1[mt][1], Ab[cur][mt], Bb[cur] + 2);
            }
        }

        // reordered staging: retire WB reads, issue next copy, THEN do epilogue (copy hides behind it)
        __syncthreads();              // all warps' WB reads (this half) done
        if (half == 0) {
            const uint4* src = g_W1img[t][1];
            for (int i = tid; i < 1344; i += 256) cp16(sb + WB_OFF + i * 16, src + i);
            CP_COMMIT();
        } else {
            const uint4* src = g_W2img[t];
            for (int i = tid; i < 1632; i += 256) cp16(sb + WB_OFF + i * 16, src + i);
            CP_COMMIT();
        }

        // epilogue 1 -> H1 cols [half*64 + nww*16, +16) (stride 272), packed celu
        #pragma unroll
        for (int mt = 0; mt < 2; mt++) {
            int row0 = mb + mt * 16 + (lane >> 2);
            #pragma unroll
            for (int nt = 0; nt < 2; nt++) {
                int col = half * 64 + nww * 16 + nt * 8 + 2 * (lane & 3);
                float* d = acc1[mt][nt];
                __half2 v01 = celu_h2(__floats2half2_rn(d[0] + sBias[160 + col], d[1] + sBias[160 + col + 1]));
                __half2 v23 = celu_h2(__floats2half2_rn(d[2] + sBias[160 + col], d[3] + sBias[160 + col + 1]));
                *(__half2*)(smem + H1_OFF + row0 * 272 + col * 2)       = v01;
                *(__half2*)(smem + H1_OFF + (row0 + 8) * 272 + col * 2) = v23;
            }
        }
        CP_WAIT(0);
        __syncthreads();              // next WB contents + H1 writes visible
    }

    // ===================== LAYER 2: 128 -> 96 (+ fused layer 3 & reduce) =====================
    float acc2[2][3][4];
    #pragma unroll
    for (int mt = 0; mt < 2; mt++)
        #pragma unroll
        for (int nt = 0; nt < 3; nt++)
            #pragma unroll
            for (int q = 0; q < 4; q++) acc2[mt][nt][q] = 0.f;

    const uint32_t aH1 = sb + H1_OFF + (mb + arow) * 272 + akb;
    const uint32_t bA2 = sb + WB_OFF + (nww * 24 + brow) * 272 + bkb;           // n16
    const uint32_t bC2 = sb + WB_OFF + (nww * 24 + 16 + brow2) * 272 + bkb2;     // n8

    {
        uint32_t Ab[2][2][4], Bb[2][4], Cb[2][2];
        ldm_x4(Ab[0][0], aH1);
        ldm_x4(Ab[0][1], aH1 + 16 * 272);
        ldm_x4(Bb[0], bA2);
        ldm_x2(Cb[0], bC2);
        #pragma unroll
        for (int ks = 0; ks < 8; ks++) {
            const int cur = ks & 1;
            if (ks < 7) {
                const uint32_t kb2 = (ks + 1) * 32;
                ldm_x4(Ab[cur ^ 1][0], aH1 + kb2);
                ldm_x4(Ab[cur ^ 1][1], aH1 + 16 * 272 + kb2);
                ldm_x4(Bb[cur ^ 1], bA2 + kb2);
                ldm_x2(Cb[cur ^ 1], bC2 + kb2);
            }
            #pragma unroll
            for (int mt = 0; mt < 2; mt++) {
                mma_fp16(acc2[mt][0], Ab[cur][mt], Bb[cur]);
                mma_fp16(acc2[mt][1], Ab[cur][mt], Bb[cur] + 2);
                mma_fp16(acc2[mt][2], Ab[cur][mt], Cb[cur]);
            }
        }
    }

    // layer-3 + molecule reduce: atomicAdd per-atom contribution into out_e
    {
        float part[2][2] = {{0.f, 0.f}, {0.f, 0.f}};
        #pragma unroll
        for (int mt = 0; mt < 2; mt++)
            #pragma unroll
            for (int nt = 0; nt < 3; nt++) {
                int col = nww * 24 + nt * 8 + 2 * (lane & 3);
                float* d = acc2[mt][nt];
                part[mt][0] += celu_f(d[0] + sBias[288 + col]) * sBias[384 + col]
                             + celu_f(d[1] + sBias[288 + col + 1]) * sBias[384 + col + 1];
                part[mt][1] += celu_f(d[2] + sBias[288 + col]) * sBias[384 + col]
                             + celu_f(d[3] + sBias[288 + col + 1]) * sBias[384 + col + 1];
            }
        #pragma unroll
        for (int mt = 0; mt < 2; mt++)
            #pragma unroll
            for (int h = 0; h < 2; h++) {
                part[mt][h] += __shfl_xor_sync(0xffffffffu, part[mt][h], 1);
                part[mt][h] += __shfl_xor_sync(0xffffffffu, part[mt][h], 2);
            }
        if ((lane & 3) == 0) {
            #pragma unroll
            for (int mt = 0; mt < 2; mt++)
                #pragma unroll
                for (int h = 0; h < 2; h++) {
                    int row = mb + mt * 16 + h * 8 + (lane >> 2);
                    int gi  = sIdx[row];
                    if (gi >= 0) {
                        float v = part[mt][h] + (nww == 0 ? sBias[480] : 0.f);
                        atomicAdd(out_e + (gi >> 6), v);
                    }
                }
        }
    }
}

extern "C" void kernel_launch(void* const* d_in, const int* in_sizes, int n_in,
                              void* d_out, int out_size)
{
    const int*   sp  = (const int*)d_in[0];
    const float* aev = (const float*)d_in[1];
    const float* W0 = (const float*)d_in[2];
    const float* b0 = (const float*)d_in[3];
    const float* W1 = (const float*)d_in[4];
    const float* b1 = (const float*)d_in[5];
    const float* W2 = (const float*)d_in[6];
    const float* b2 = (const float*)d_in[7];
    const float* W3 = (const float*)d_in[8];
    const float* b3 = (const float*)d_in[9];

    float* out = (float*)d_out;
    float* out_head;
    float* out_e;
    if (out_size == NB) { out_head = nullptr; out_e = out; }
    else                { out_head = out;     out_e = out + (out_size - NB); }

    k_detect    <<<1, 32>>>(sp);
    k_count_prep<<<CP_GRID, 256>>>(sp, W0, W1, W2);
    k_scatter   <<<NATOMS / 256, 256>>>(sp, out_head, out_e);

    cudaFuncSetAttribute(k_mlp_tc, cudaFuncAttributeMaxDynamicSharedMemorySize, SM_TOTAL);
    k_mlp_tc<<<MAXTILES, 256, SM_TOTAL>>>(aev, b0, b1, b2, W3, b3, out_e);
}

// round 15
// speedup vs baseline: 1.6371x; 1.0345x over previous
#include <cuda_runtime.h>
#include <cuda_fp16.h>
#include <cstdint>

// ---------------- problem constants ----------------
#define NB      2048
#define NA      64
#define NATOMS  (NB*NA)
#define AEV     384
#define N0      160
#define N1      128
#define N2      96
#define NTYPES  4
#define TILE    64
#define MAXTILES 2056

// ---------------- device scratch ----------------
__device__ int   g_is64;
__device__ int   g_counts[NTYPES];
__device__ int   g_cursor[NTYPES];
__device__ int   g_perm[NATOMS];

// fp16 weight images, [n][k] layout, padded strides (bytes): W0 208, W1 336, W2 272
__device__ uint4 g_W0img[NTYPES][4][2080];   // per 96-K chunk: 160*208 B
__device__ uint4 g_W1img[NTYPES][2][1344];   // per 64-N half:  64*336 B (K=160)
__device__ uint4 g_W2img[NTYPES][1632];      // 96*272 B (K=128)

__device__ __forceinline__ float celu_f(float x) {
    return x > 0.f ? x : 0.1f * (__expf(10.f * x) - 1.f);
}
__device__ __forceinline__ __half2 celu_h2(__half2 x) {
    const __half2 ZERO  = __float2half2_rn(0.f);
    const __half2 ONE   = __float2half2_rn(1.f);
    const __half2 TEN   = __float2half2_rn(10.f);
    const __half2 TENTH = __float2half2_rn(0.1f);
    __half2 xa  = __hmin2(x, ZERO);
    __half2 ex  = h2exp(__hmul2(xa, TEN));
    __half2 neg = __hmul2(__hsub2(ex, ONE), TENTH);
    __half2 m   = __hgt2(x, ZERO);
    return __hfma2(m, __hsub2(x, neg), neg);
}
__device__ __forceinline__ int get_sp(const int* __restrict__ raw, int i, int is64) {
    return is64 ? raw[2 * i] : raw[i];
}
__device__ __forceinline__ uint32_t pack2h(float a, float b) {
    __half ha = __float2half_rn(a), hb = __float2half_rn(b);
    return (uint32_t)__half_as_ushort(ha) | ((uint32_t)__half_as_ushort(hb) << 16);
}
__device__ __forceinline__ uint32_t h2_u32(__half2 h) {
    return *(uint32_t*)&h;
}
__device__ __forceinline__ uint32_t smem_u32(const void* p) {
    uint32_t a;
    asm("{ .reg .u64 t; cvta.to.shared.u64 t, %1; cvt.u32.u64 %0, t; }" : "=r"(a) : "l"(p));
    return a;
}
__device__ __forceinline__ void ldm_x4(uint32_t* r, uint32_t addr) {
    asm volatile("ldmatrix.sync.aligned.m8n8.x4.shared.b16 {%0,%1,%2,%3}, [%4];"
                 : "=r"(r[0]), "=r"(r[1]), "=r"(r[2]), "=r"(r[3]) : "r"(addr));
}
__device__ __forceinline__ void ldm_x2(uint32_t* r, uint32_t addr) {
    asm volatile("ldmatrix.sync.aligned.m8n8.x2.shared.b16 {%0,%1}, [%2];"
                 : "=r"(r[0]), "=r"(r[1]) : "r"(addr));
}
__device__ __forceinline__ void mma_fp16(float* d, const uint32_t* a, const uint32_t* b) {
    asm volatile(
        "mma.sync.aligned.m16n8k16.row.col.f32.f16.f16.f32 "
        "{%0,%1,%2,%3},{%4,%5,%6,%7},{%8,%9},{%0,%1,%2,%3};"
        : "+f"(d[0]), "+f"(d[1]), "+f"(d[2]), "+f"(d[3])
        : "r"(a[0]), "r"(a[1]), "r"(a[2]), "r"(a[3]), "r"(b[0]), "r"(b[1]));
}
__device__ __forceinline__ void cp16(uint32_t s, const void* g) {
    asm volatile("cp.async.cg.shared.global [%0], [%1], 16;" :: "r"(s), "l"(g) : "memory");
}
#define CP_COMMIT() asm volatile("cp.async.commit_group;" ::: "memory")
#define CP_WAIT(n)  asm volatile("cp.async.wait_group %0;" :: "n"(n) : "memory")

// ---------------- launch 1: dtype probe + reset ----------------
__global__ void k_detect(const int* __restrict__ sp_raw) {
    if (threadIdx.x == 0) {
        int odd_nonzero = 0;
        #pragma unroll
        for (int i = 1; i < 64; i += 2) odd_nonzero |= (sp_raw[i] != 0);
        g_is64 = odd_nonzero ? 0 : 1;
    }
    if (threadIdx.x < NTYPES) { g_counts[threadIdx.x] = 0; g_cursor[threadIdx.x] = 0; }
}

// ---------------- launch 2: count + weight prep (fused) ----------------
#define PREP_W0 122880   // 4t * 4c * 160n * 48j
#define PREP_W1 40960    // 4t * 2h * 64n * 80j
#define PREP_W2 24576    // 4t * 96n * 64j
#define PREP_TOTAL (PREP_W0 + PREP_W1 + PREP_W2)
#define CP_GRID ((PREP_TOTAL + 255) / 256)

__global__ void k_count_prep(const int* __restrict__ sp,
                             const float* __restrict__ W0, const float* __restrict__ W1,
                             const float* __restrict__ W2) {
    int gid = blockIdx.x * blockDim.x + threadIdx.x;

    __shared__ int c[NTYPES];
    if (threadIdx.x < NTYPES) c[threadIdx.x] = 0;
    __syncthreads();
    if (gid < NATOMS) {
        int t = get_sp(sp, gid, g_is64);
        if ((unsigned)t < NTYPES) atomicAdd(&c[t], 1);
    }
    __syncthreads();
    if (threadIdx.x < NTYPES && c[threadIdx.x]) atomicAdd(&g_counts[threadIdx.x], c[threadIdx.x]);

    int idx = gid;
    if (idx < PREP_W0) {
        int t = idx / 30720, r = idx % 30720;
        int cc = r / 7680;  r %= 7680;
        int n = r / 48, j = r % 48;
        int k0 = cc * 96 + 2 * j;
        float v0 = W0[((size_t)t * AEV + k0)     * N0 + n];
        float v1 = W0[((size_t)t * AEV + k0 + 1) * N0 + n];
        *(uint32_t*)((char*)g_W0img[t][cc] + n * 208 + j * 4) = pack2h(v0, v1);
    } else if (idx < PREP_W0 + PREP_W1) {
        int i2 = idx - PREP_W0;
        int t = i2 / 10240, r = i2 % 10240;
        int h = r / 5120;  r %= 5120;
        int n = r / 80, j = r % 80;
        int k0 = 2 * j;
        float v0 = W1[((size_t)t * N0 + k0)     * N1 + h * 64 + n];
        float v1 = W1[((size_t)t * N0 + k0 + 1) * N1 + h * 64 + n];
        *(uint32_t*)((char*)g_W1img[t][h] + n * 336 + j * 4) = pack2h(v0, v1);
    } else if (idx < PREP_TOTAL) {
        int i3 = idx - PREP_W0 - PREP_W1;
        int t = i3 / 6144, r = i3 % 6144;
        int n = r / 64, j = r % 64;
        int k0 = 2 * j;
        float v0 = W2[((size_t)t * N1 + k0)     * N2 + n];
        float v1 = W2[((size_t)t * N1 + k0 + 1) * N2 + n];
        *(uint32_t*)((char*)g_W2img[t] + n * 272 + j * 4) = pack2h(v0, v1);
    }
}

// ---------------- launch 3: scatter + output-head + out_e zero ----------------
__global__ void k_scatter(const int* __restrict__ sp,
                          float* __restrict__ out_head,
                          float* __restrict__ out_e) {
    __shared__ int soff[NTYPES];
    __shared__ int base[NTYPES];
    __shared__ int lc[NTYPES];
    if (threadIdx.x == 0) {
        int o = 0;
        #pragma unroll
        for (int t = 0; t < NTYPES; t++) { soff[t] = o; o += g_counts[t]; }
    }
    if (threadIdx.x < NTYPES) lc[threadIdx.x] = 0;
    __syncthreads();
    int i = blockIdx.x * blockDim.x + threadIdx.x;
    if (i < NB) out_e[i] = 0.f;
    int t = -1, r = 0;
    if (i < NATOMS) {
        int tv = get_sp(sp, i, g_is64);
        if (out_head) out_head[i] = (float)tv;
        if ((unsigned)tv < NTYPES) { t = tv; r = atomicAdd(&lc[t], 1); }
    }
    __syncthreads();
    if (threadIdx.x < NTYPES)
        base[threadIdx.x] = lc[threadIdx.x] ? atomicAdd(&g_cursor[threadIdx.x], lc[threadIdx.x]) : 0;
    __syncthreads();
    if (t >= 0) g_perm[soff[t] + base[t] + r] = i;
}

// ---------------- launch 4: fused MLP (64-atom tiles, 2Mx4N warps, A-pipelined) ----------------
#define BIAS_OFF 0
#define SIDX_OFF 1936
#define WB_OFF   2560
#define X_OFF    35840
#define H1_OFF   35840
#define H0_OFF   53248
#define SM_TOTAL 74752

__global__ __launch_bounds__(256, 3)
void k_mlp_tc(const float* __restrict__ aev,
              const float* __restrict__ b0, const float* __restrict__ b1,
              const float* __restrict__ b2, const float* __restrict__ W3,
              const float* __restrict__ b3,
              float* __restrict__ out_e)
{
    // derive this CTA's tile (type, start, len) from g_counts
    int t = -1, gstart = 0, len = 0;
    {
        int rem = blockIdx.x, off = 0;
        #pragma unroll
        for (int tt = 0; tt < NTYPES; tt++) {
            int cc = g_counts[tt];
            int ntl = (cc + TILE - 1) / TILE;
            if (t < 0) {
                if (rem < ntl) {
                    t = tt;
                    gstart = off + rem * TILE;
                    int l = cc - rem * TILE;
                    len = l < TILE ? l : TILE;
                } else rem -= ntl;
            }
            off += cc;
        }
    }
    if (t < 0) return;

    extern __shared__ char smem[];
    const uint32_t sb = smem_u32(smem);
    float* sBias = (float*)(smem + BIAS_OFF);
    int*   sIdx  = (int*)(smem + SIDX_OFF);

    const int tid  = threadIdx.x;
    const int lane = tid & 31;
    const int w    = tid >> 5;
    const int mw   = w & 1;         // M group (0/1)
    const int nww  = w >> 1;        // N group (0..3)
    const int mb   = mw * 32;

    if (tid < TILE) sIdx[tid] = (tid < len) ? g_perm[gstart + tid] : -1;
    for (int i = tid; i < N0; i += 256) sBias[i] = b0[t * N0 + i];
    for (int i = tid; i < N1; i += 256) sBias[160 + i] = b1[t * N1 + i];
    for (int i = tid; i < N2; i += 256) { sBias[288 + i] = b2[t * N2 + i]; sBias[384 + i] = W3[t * N2 + i]; }
    if (tid == 0) sBias[480] = b3[t];

    // prefetch W0 chunk 0
    {
        const uint4* src = g_W0img[t][0];
        for (int i = tid; i < 2080; i += 256) cp16(sb + WB_OFF + i * 16, src + i);
        CP_COMMIT();
    }
    __syncthreads();

    // lane offsets for ldmatrix
    const int arow  = (lane & 7) + (lane & 8);
    const int akb   = (lane & 16) ? 16 : 0;
    const int brow  = (lane & 7) + ((lane & 16) ? 8 : 0);
    const int bkb   = (lane & 8) ? 16 : 0;
    const int brow2 = (lane & 7);               // x2/x4 B (n8)
    const int bkb2  = (lane & 8) ? 16 : 0;      // x2 (n8k16)
    const int bkb4  = (lane >> 3) * 16;         // x4 (n8k32)

    // ===================== LAYER 0: 384 -> 160 =====================
    float acc0[2][5][4];
    #pragma unroll
    for (int mt = 0; mt < 2; mt++)
        #pragma unroll
        for (int nt = 0; nt < 5; nt++)
            #pragma unroll
            for (int q = 0; q < 4; q++) acc0[mt][nt][q] = 0.f;

    const uint32_t aX   = sb + X_OFF + (mb + arow) * 208 + akb;
    const uint32_t bA0  = sb + WB_OFF + (nww * 40 + brow) * 208 + bkb;           // n16 @ +0
    const uint32_t bB0  = bA0 + 16 * 208;                                         // n16 @ +16
    const uint32_t bC04 = sb + WB_OFF + (nww * 40 + 32 + brow2) * 208 + bkb4;     // n8 k32 (x4)

    const int srow  = tid >> 2;
    const int scol0 = (tid & 3) * 24;

    for (int c = 0; c < 4; c++) {
        // stage X chunk c: row = tid/4 (0..63), 24 cols per quarter-thread, batched 16B stores
        {
            int gi = sIdx[srow];
            const float4* src = (const float4*)(aev + (size_t)(gi < 0 ? 0 : gi) * AEV + c * 96 + scol0);
            uint4* dx = (uint4*)(smem + X_OFF + srow * 208 + scol0 * 2);
            #pragma unroll
            for (int i = 0; i < 3; i++) {
                float4 v0 = (gi >= 0) ? src[2 * i]     : make_float4(0.f, 0.f, 0.f, 0.f);
                float4 v1 = (gi >= 0) ? src[2 * i + 1] : make_float4(0.f, 0.f, 0.f, 0.f);
                uint4 o;
                o.x = h2_u32(__floats2half2_rn(v0.x, v0.y));
                o.y = h2_u32(__floats2half2_rn(v0.z, v0.w));
                o.z = h2_u32(__floats2half2_rn(v1.x, v1.y));
                o.w = h2_u32(__floats2half2_rn(v1.z, v1.w));
                dx[i] = o;
            }
        }
        CP_WAIT(0);
        __syncthreads();          // W0 chunk + X ready

        uint32_t Ab[2][2][4];
        ldm_x4(Ab[0][0], aX);
        ldm_x4(Ab[0][1], aX + 16 * 208);
        uint32_t C4[4];
        #pragma unroll
        for (int ks = 0; ks < 6; ks++) {
            const uint32_t kb = ks * 32;
            const int cur = ks & 1;
            if ((ks & 1) == 0) ldm_x4(C4, bC04 + (ks >> 1) * 64);   // n8 x k32: covers ks, ks+1
            uint32_t B0[4], B1[4];
            ldm_x4(B0, bA0 + kb);
            ldm_x4(B1, bB0 + kb);
            if (ks < 5) {         // prefetch A for next ks
                ldm_x4(Ab[cur ^ 1][0], aX + kb + 32);
                ldm_x4(Ab[cur ^ 1][1], aX + 16 * 208 + kb + 32);
            }
            #pragma unroll
            for (int mt = 0; mt < 2; mt++) {
                mma_fp16(acc0[mt][0], Ab[cur][mt], B0);
                mma_fp16(acc0[mt][1], Ab[cur][mt], B0 + 2);
                mma_fp16(acc0[mt][2], Ab[cur][mt], B1);
                mma_fp16(acc0[mt][3], Ab[cur][mt], B1 + 2);
                mma_fp16(acc0[mt][4], Ab[cur][mt], C4 + (ks & 1) * 2);
            }
        }
        __syncthreads();          // all reads of X/WB done before overwrite

        if (c < 3) {
            const uint4* src = g_W0img[t][c + 1];
            for (int i = tid; i < 2080; i += 256) cp16(sb + WB_OFF + i * 16, src + i);
            CP_COMMIT();
        }
    }

    // prefetch W1 half 0 into WB (overlaps epilogue 0)
    {
        const uint4* src = g_W1img[t][0];
        for (int i = tid; i < 1344; i += 256) cp16(sb + WB_OFF + i * 16, src + i);
        CP_COMMIT();
    }

    // epilogue 0 -> H0 (stride 336), packed celu
    #pragma unroll
    for (int mt = 0; mt < 2; mt++) {
        int row0 = mb + mt * 16 + (lane >> 2);
        #pragma unroll
        for (int nt = 0; nt < 5; nt++) {
            int col = nww * 40 + nt * 8 + 2 * (lane & 3);
            float* d = acc0[mt][nt];
            __half2 v01 = celu_h2(__floats2half2_rn(d[0] + sBias[col], d[1] + sBias[col + 1]));
            __half2 v23 = celu_h2(__floats2half2_rn(d[2] + sBias[col], d[3] + sBias[col + 1]));
            *(__half2*)(smem + H0_OFF + row0 * 336 + col * 2)       = v01;
            *(__half2*)(smem + H0_OFF + (row0 + 8) * 336 + col * 2) = v23;
        }
    }
    CP_WAIT(0);
    __syncthreads();

    // ===================== LAYER 1: 160 -> 128 (two 64-N halves) =====================
    const uint32_t aH0 = sb + H0_OFF + (mb + arow) * 336 + akb;
    const uint32_t bW1 = sb + WB_OFF + (nww * 16 + brow) * 336 + bkb;   // n16 per warp per half

    for (int half = 0; half < 2; half++) {
        float acc1[2][2][4];
        #pragma unroll
        for (int mt = 0; mt < 2; mt++)
            #pragma unroll
            for (int nt = 0; nt < 2; nt++)
                #pragma unroll
                for (int q = 0; q < 4; q++) acc1[mt][nt][q] = 0.f;

        uint32_t Ab[2][2][4], Bb[2][4];
        ldm_x4(Ab[0][0], aH0);
        ldm_x4(Ab[0][1], aH0 + 16 * 336);
        ldm_x4(Bb[0], bW1);
        #pragma unroll
        for (int ks = 0; ks < 10; ks++) {
            const int cur = ks & 1;
            if (ks < 9) {
                const uint32_t kb2 = (ks + 1) * 32;
                ldm_x4(Ab[cur ^ 1][0], aH0 + kb2);
                ldm_x4(Ab[cur ^ 1][1], aH0 + 16 * 336 + kb2);
                ldm_x4(Bb[cur ^ 1], bW1 + kb2);
            }
            #pragma unroll
            for (int mt = 0; mt < 2; mt++) {
                mma_fp16(acc1[mt][0], Ab[cur][mt], Bb[cur]);
                mma_fp16(acc1[mt][1], Ab[cur][mt], Bb[cur] + 2);
            }
        }

        // reordered staging: retire WB reads, issue next copy, THEN do epilogue (copy hides behind it)
        __syncthreads();              // all warps' WB reads (this half) done
        if (half == 0) {
            const uint4* src = g_W1img[t][1];
            for (int i = tid; i < 1344; i += 256) cp16(sb + WB_OFF + i * 16, src + i);
            CP_COMMIT();
        } else {
            const uint4* src = g_W2img[t];
            for (int i = tid; i < 1632; i += 256) cp16(sb + WB_OFF + i * 16, src + i);
            CP_COMMIT();
        }

        // epilogue 1 -> H1 cols [half*64 + nww*16, +16) (stride 272), packed celu
        #pragma unroll
        for (int mt = 0; mt < 2; mt++) {
            int row0 = mb + mt * 16 + (lane >> 2);
            #pragma unroll
            for (int nt = 0; nt < 2; nt++) {
                int col = half * 64 + nww * 16 + nt * 8 + 2 * (lane & 3);
                float* d = acc1[mt][nt];
                __half2 v01 = celu_h2(__floats2half2_rn(d[0] + sBias[160 + col], d[1] + sBias[160 + col + 1]));
                __half2 v23 = celu_h2(__floats2half2_rn(d[2] + sBias[160 + col], d[3] + sBias[160 + col + 1]));
                *(__half2*)(smem + H1_OFF + row0 * 272 + col * 2)       = v01;
                *(__half2*)(smem + H1_OFF + (row0 + 8) * 272 + col * 2) = v23;
            }
        }
        CP_WAIT(0);
        __syncthreads();              // next WB contents + H1 writes visible
    }

    // ===================== LAYER 2: 128 -> 96 (+ fused layer 3 & reduce) =====================
    float acc2[2][3][4];
    #pragma unroll
    for (int mt = 0; mt < 2; mt++)
        #pragma unroll
        for (int nt = 0; nt < 3; nt++)
            #pragma unroll
            for (int q = 0; q < 4; q++) acc2[mt][nt][q] = 0.f;

    const uint32_t aH1 = sb + H1_OFF + (mb + arow) * 272 + akb;
    const uint32_t bA2 = sb + WB_OFF + (nww * 24 + brow) * 272 + bkb;            // n16
    const uint32_t bC24 = sb + WB_OFF + (nww * 24 + 16 + brow2) * 272 + bkb4;    // n8 k32 (x4)

    {
        uint32_t Ab[2][2][4], Bb[2][4], C4[4];
        ldm_x4(Ab[0][0], aH1);
        ldm_x4(Ab[0][1], aH1 + 16 * 272);
        ldm_x4(Bb[0], bA2);
        #pragma unroll
        for (int ks = 0; ks < 8; ks++) {
            const int cur = ks & 1;
            if ((ks & 1) == 0) ldm_x4(C4, bC24 + (ks >> 1) * 64);   // n8 x k32
            if (ks < 7) {
                const uint32_t kb2 = (ks + 1) * 32;
                ldm_x4(Ab[cur ^ 1][0], aH1 + kb2);
                ldm_x4(Ab[cur ^ 1][1], aH1 + 16 * 272 + kb2);
                ldm_x4(Bb[cur ^ 1], bA2 + kb2);
            }
            #pragma unroll
            for (int mt = 0; mt < 2; mt++) {
                mma_fp16(acc2[mt][0], Ab[cur][mt], Bb[cur]);
                mma_fp16(acc2[mt][1], Ab[cur][mt], Bb[cur] + 2);
                mma_fp16(acc2[mt][2], Ab[cur][mt], C4 + (ks & 1) * 2);
            }
        }
    }

    // layer-3 + molecule reduce: atomicAdd per-atom contribution into out_e
    {
        float part[2][2] = {{0.f, 0.f}, {0.f, 0.f}};
        #pragma unroll
        for (int mt = 0; mt < 2; mt++)
            #pragma unroll
            for (int nt = 0; nt < 3; nt++) {
                int col = nww * 24 + nt * 8 + 2 * (lane & 3);
                float* d = acc2[mt][nt];
                part[mt][0] += celu_f(d[0] + sBias[288 + col]) * sBias[384 + col]
                             + celu_f(d[1] + sBias[288 + col + 1]) * sBias[384 + col + 1];
                part[mt][1] += celu_f(d[2] + sBias[288 + col]) * sBias[384 + col]
                             + celu_f(d[3] + sBias[288 + col + 1]) * sBias[384 + col + 1];
            }
        #pragma unroll
        for (int mt = 0; mt < 2; mt++)
            #pragma unroll
            for (int h = 0; h < 2; h++) {
                part[mt][h] += __shfl_xor_sync(0xffffffffu, part[mt][h], 1);
                part[mt][h] += __shfl_xor_sync(0xffffffffu, part[mt][h], 2);
            }
        if ((lane & 3) == 0) {
            #pragma unroll
            for (int mt = 0; mt < 2; mt++)
                #pragma unroll
                for (int h = 0; h < 2; h++) {
                    int row = mb + mt * 16 + h * 8 + (lane >> 2);
                    int gi  = sIdx[row];
                    if (gi >= 0) {
                        float v = part[mt][h] + (nww == 0 ? sBias[480] : 0.f);
                        atomicAdd(out_e + (gi >> 6), v);
                    }
                }
        }
    }
}

extern "C" void kernel_launch(void* const* d_in, const int* in_sizes, int n_in,
                              void* d_out, int out_size)
{
    const int*   sp  = (const int*)d_in[0];
    const float* aev = (const float*)d_in[1];
    const float* W0 = (const float*)d_in[2];
    const float* b0 = (const float*)d_in[3];
    const float* W1 = (const float*)d_in[4];
    const float* b1 = (const float*)d_in[5];
    const float* W2 = (const float*)d_in[6];
    const float* b2 = (const float*)d_in[7];
    const float* W3 = (const float*)d_in[8];
    const float* b3 = (const float*)d_in[9];

    float* out = (float*)d_out;
    float* out_head;
    float* out_e;
    if (out_size == NB) { out_head = nullptr; out_e = out; }
    else                { out_head = out;     out_e = out + (out_size - NB); }

    k_detect    <<<1, 32>>>(sp);
    k_count_prep<<<CP_GRID, 256>>>(sp, W0, W1, W2);
    k_scatter   <<<NATOMS / 256, 256>>>(sp, out_head, out_e);

    cudaFuncSetAttribute(k_mlp_tc, cudaFuncAttributeMaxDynamicSharedMemorySize, SM_TOTAL);
    k_mlp_tc<<<MAXTILES, 256, SM_TOTAL>>>(aev, b0, b1, b2, W3, b3, out_e);
}

// round 16
// speedup vs baseline: 1.6587x; 1.0132x over previous
#include <cuda_runtime.h>
#include <cuda_fp16.h>
#include <cstdint>

// ---------------- problem constants ----------------
#define NB      2048
#define NA      64
#define NATOMS  (NB*NA)
#define AEV     384
#define N0      160
#define N1      128
#define N2      96
#define NTYPES  4
#define TILE    64
#define MAXTILES 2056

// ---------------- device scratch ----------------
__device__ int   g_is64;
__device__ int   g_counts[NTYPES];            // doubles as placement cursor during k_fused
__device__ int   g_perm4[NTYPES][NATOMS];     // per-type permutation (no cross-type offsets)

// fp16 weight images, [n][k] layout, padded strides (bytes): W0 208, W1 336, W2 272
__device__ uint4 g_W0img[NTYPES][4][2080];   // per 96-K chunk: 160*208 B
__device__ uint4 g_W1img[NTYPES][2][1344];   // per 64-N half:  64*336 B (K=160)
__device__ uint4 g_W2img[NTYPES][1632];      // 96*272 B (K=128)

__device__ __forceinline__ float celu_f(float x) {
    return x > 0.f ? x : 0.1f * (__expf(10.f * x) - 1.f);
}
__device__ __forceinline__ __half2 celu_h2(__half2 x) {
    const __half2 ZERO  = __float2half2_rn(0.f);
    const __half2 ONE   = __float2half2_rn(1.f);
    const __half2 TEN   = __float2half2_rn(10.f);
    const __half2 TENTH = __float2half2_rn(0.1f);
    __half2 xa  = __hmin2(x, ZERO);
    __half2 ex  = h2exp(__hmul2(xa, TEN));
    __half2 neg = __hmul2(__hsub2(ex, ONE), TENTH);
    __half2 m   = __hgt2(x, ZERO);
    return __hfma2(m, __hsub2(x, neg), neg);
}
__device__ __forceinline__ int get_sp(const int* __restrict__ raw, int i, int is64) {
    return is64 ? raw[2 * i] : raw[i];
}
__device__ __forceinline__ uint32_t pack2h(float a, float b) {
    __half ha = __float2half_rn(a), hb = __float2half_rn(b);
    return (uint32_t)__half_as_ushort(ha) | ((uint32_t)__half_as_ushort(hb) << 16);
}
__device__ __forceinline__ uint32_t h2_u32(__half2 h) {
    return *(uint32_t*)&h;
}
__device__ __forceinline__ uint32_t smem_u32(const void* p) {
    uint32_t a;
    asm("{ .reg .u64 t; cvta.to.shared.u64 t, %1; cvt.u32.u64 %0, t; }" : "=r"(a) : "l"(p));
    return a;
}
__device__ __forceinline__ void ldm_x4(uint32_t* r, uint32_t addr) {
    asm volatile("ldmatrix.sync.aligned.m8n8.x4.shared.b16 {%0,%1,%2,%3}, [%4];"
                 : "=r"(r[0]), "=r"(r[1]), "=r"(r[2]), "=r"(r[3]) : "r"(addr));
}
__device__ __forceinline__ void mma_fp16(float* d, const uint32_t* a, const uint32_t* b) {
    asm volatile(
        "mma.sync.aligned.m16n8k16.row.col.f32.f16.f16.f32 "
        "{%0,%1,%2,%3},{%4,%5,%6,%7},{%8,%9},{%0,%1,%2,%3};"
        : "+f"(d[0]), "+f"(d[1]), "+f"(d[2]), "+f"(d[3])
        : "r"(a[0]), "r"(a[1]), "r"(a[2]), "r"(a[3]), "r"(b[0]), "r"(b[1]));
}
__device__ __forceinline__ void cp16(uint32_t s, const void* g) {
    asm volatile("cp.async.cg.shared.global [%0], [%1], 16;" :: "r"(s), "l"(g) : "memory");
}
#define CP_COMMIT() asm volatile("cp.async.commit_group;" ::: "memory")
#define CP_WAIT(n)  asm volatile("cp.async.wait_group %0;" :: "n"(n) : "memory")

// ---------------- launch 1: dtype probe + counter reset ----------------
__global__ void k_detect(const int* __restrict__ sp_raw) {
    if (threadIdx.x == 0) {
        int odd_nonzero = 0;
        #pragma unroll
        for (int i = 1; i < 64; i += 2) odd_nonzero |= (sp_raw[i] != 0);
        g_is64 = odd_nonzero ? 0 : 1;
    }
    if (threadIdx.x < NTYPES) g_counts[threadIdx.x] = 0;
}

// ---------------- launch 2: fused count + scatter + weight prep + output head ----------------
#define PREP_W0 122880   // 4t * 4c * 160n * 48j
#define PREP_W1 40960    // 4t * 2h * 64n * 80j
#define PREP_W2 24576    // 4t * 96n * 64j
#define PREP_TOTAL (PREP_W0 + PREP_W1 + PREP_W2)
#define CP_GRID ((PREP_TOTAL + 255) / 256)

__global__ void k_fused(const int* __restrict__ sp,
                        const float* __restrict__ W0, const float* __restrict__ W1,
                        const float* __restrict__ W2,
                        float* __restrict__ out_head, float* __restrict__ out_e) {
    int gid = blockIdx.x * blockDim.x + threadIdx.x;

    // ---- scatter part (two-level: smem rank, one global atomic per type/block) ----
    __shared__ int lc[NTYPES];
    __shared__ int base[NTYPES];
    if (threadIdx.x < NTYPES) lc[threadIdx.x] = 0;
    __syncthreads();
    if (gid < NB) out_e[gid] = 0.f;
    int t = -1, r = 0;
    if (gid < NATOMS) {
        int tv = get_sp(sp, gid, g_is64);
        if (out_head) out_head[gid] = (float)tv;
        if ((unsigned)tv < NTYPES) { t = tv; r = atomicAdd(&lc[t], 1); }
    }
    __syncthreads();
    if (threadIdx.x < NTYPES)
        base[threadIdx.x] = lc[threadIdx.x] ? atomicAdd(&g_counts[threadIdx.x], lc[threadIdx.x]) : 0;
    __syncthreads();
    if (t >= 0) g_perm4[t][base[t] + r] = gid;

    // ---- weight prep part ----
    int idx = gid;
    if (idx < PREP_W0) {
        int tt = idx / 30720, rr = idx % 30720;
        int cc = rr / 7680;  rr %= 7680;
        int n = rr / 48, j = rr % 48;
        int k0 = cc * 96 + 2 * j;
        float v0 = W0[((size_t)tt * AEV + k0)     * N0 + n];
        float v1 = W0[((size_t)tt * AEV + k0 + 1) * N0 + n];
        *(uint32_t*)((char*)g_W0img[tt][cc] + n * 208 + j * 4) = pack2h(v0, v1);
    } else if (idx < PREP_W0 + PREP_W1) {
        int i2 = idx - PREP_W0;
        int tt = i2 / 10240, rr = i2 % 10240;
        int h = rr / 5120;  rr %= 5120;
        int n = rr / 80, j = rr % 80;
        int k0 = 2 * j;
        float v0 = W1[((size_t)tt * N0 + k0)     * N1 + h * 64 + n];
        float v1 = W1[((size_t)tt * N0 + k0 + 1) * N1 + h * 64 + n];
        *(uint32_t*)((char*)g_W1img[tt][h] + n * 336 + j * 4) = pack2h(v0, v1);
    } else if (idx < PREP_TOTAL) {
        int i3 = idx - PREP_W0 - PREP_W1;
        int tt = i3 / 6144, rr = i3 % 6144;
        int n = rr / 64, j = rr % 64;
        int k0 = 2 * j;
        float v0 = W2[((size_t)tt * N1 + k0)     * N2 + n];
        float v1 = W2[((size_t)tt * N1 + k0 + 1) * N2 + n];
        *(uint32_t*)((char*)g_W2img[tt] + n * 272 + j * 4) = pack2h(v0, v1);
    }
}

// ---------------- launch 3: fused MLP (64-atom tiles, 2Mx4N warps, A-pipelined) ----------------
#define BIAS_OFF 0
#define SIDX_OFF 1936
#define WB_OFF   2560
#define X_OFF    35840
#define H1_OFF   35840
#define H0_OFF   53248
#define SM_TOTAL 74752

__global__ __launch_bounds__(256, 3)
void k_mlp_tc(const float* __restrict__ aev,
              const float* __restrict__ b0, const float* __restrict__ b1,
              const float* __restrict__ b2, const float* __restrict__ W3,
              const float* __restrict__ b3,
              float* __restrict__ out_e)
{
    // derive this CTA's tile (type, within-type start, len) from g_counts
    int t = -1, gstart = 0, len = 0;
    {
        int rem = blockIdx.x;
        #pragma unroll
        for (int tt = 0; tt < NTYPES; tt++) {
            int cc = g_counts[tt];
            int ntl = (cc + TILE - 1) / TILE;
            if (t < 0) {
                if (rem < ntl) {
                    t = tt;
                    gstart = rem * TILE;
                    int l = cc - gstart;
                    len = l < TILE ? l : TILE;
                } else rem -= ntl;
            }
        }
    }
    if (t < 0) return;

    extern __shared__ char smem[];
    const uint32_t sb = smem_u32(smem);
    float* sBias = (float*)(smem + BIAS_OFF);
    int*   sIdx  = (int*)(smem + SIDX_OFF);

    const int tid  = threadIdx.x;
    const int lane = tid & 31;
    const int w    = tid >> 5;
    const int mw   = w & 1;         // M group (0/1)
    const int nww  = w >> 1;        // N group (0..3)
    const int mb   = mw * 32;

    if (tid < TILE) sIdx[tid] = (tid < len) ? g_perm4[t][gstart + tid] : -1;
    for (int i = tid; i < N0; i += 256) sBias[i] = b0[t * N0 + i];
    for (int i = tid; i < N1; i += 256) sBias[160 + i] = b1[t * N1 + i];
    for (int i = tid; i < N2; i += 256) { sBias[288 + i] = b2[t * N2 + i]; sBias[384 + i] = W3[t * N2 + i]; }
    if (tid == 0) sBias[480] = b3[t];

    // prefetch W0 chunk 0
    {
        const uint4* src = g_W0img[t][0];
        for (int i = tid; i < 2080; i += 256) cp16(sb + WB_OFF + i * 16, src + i);
        CP_COMMIT();
    }
    __syncthreads();

    // lane offsets for ldmatrix
    const int arow  = (lane & 7) + (lane & 8);
    const int akb   = (lane & 16) ? 16 : 0;
    const int brow  = (lane & 7) + ((lane & 16) ? 8 : 0);
    const int bkb   = (lane & 8) ? 16 : 0;
    const int brow2 = (lane & 7);               // x4 B (n8)
    const int bkb4  = (lane >> 3) * 16;         // x4 (n8k32)

    // ===================== LAYER 0: 384 -> 160 =====================
    float acc0[2][5][4];
    #pragma unroll
    for (int mt = 0; mt < 2; mt++)
        #pragma unroll
        for (int nt = 0; nt < 5; nt++)
            #pragma unroll
            for (int q = 0; q < 4; q++) acc0[mt][nt][q] = 0.f;

    const uint32_t aX   = sb + X_OFF + (mb + arow) * 208 + akb;
    const uint32_t bA0  = sb + WB_OFF + (nww * 40 + brow) * 208 + bkb;           // n16 @ +0
    const uint32_t bB0  = bA0 + 16 * 208;                                         // n16 @ +16
    const uint32_t bC04 = sb + WB_OFF + (nww * 40 + 32 + brow2) * 208 + bkb4;     // n8 k32 (x4)

    const int srow  = tid >> 2;
    const int scol0 = (tid & 3) * 24;

    for (int c = 0; c < 4; c++) {
        // stage X chunk c: row = tid/4 (0..63), 24 cols per quarter-thread, batched 16B stores
        {
            int gi = sIdx[srow];
            const float4* src = (const float4*)(aev + (size_t)(gi < 0 ? 0 : gi) * AEV + c * 96 + scol0);
            uint4* dx = (uint4*)(smem + X_OFF + srow * 208 + scol0 * 2);
            #pragma unroll
            for (int i = 0; i < 3; i++) {
                float4 v0 = (gi >= 0) ? src[2 * i]     : make_float4(0.f, 0.f, 0.f, 0.f);
                float4 v1 = (gi >= 0) ? src[2 * i + 1] : make_float4(0.f, 0.f, 0.f, 0.f);
                uint4 o;
                o.x = h2_u32(__floats2half2_rn(v0.x, v0.y));
                o.y = h2_u32(__floats2half2_rn(v0.z, v0.w));
                o.z = h2_u32(__floats2half2_rn(v1.x, v1.y));
                o.w = h2_u32(__floats2half2_rn(v1.z, v1.w));
                dx[i] = o;
            }
        }
        CP_WAIT(0);
        __syncthreads();          // W0 chunk + X ready

        uint32_t Ab[2][2][4];
        ldm_x4(Ab[0][0], aX);
        ldm_x4(Ab[0][1], aX + 16 * 208);
        uint32_t C4[4];
        #pragma unroll
        for (int ks = 0; ks < 6; ks++) {
            const uint32_t kb = ks * 32;
            const int cur = ks & 1;
            if ((ks & 1) == 0) ldm_x4(C4, bC04 + (ks >> 1) * 64);   // n8 x k32: covers ks, ks+1
            uint32_t B0[4], B1[4];
            ldm_x4(B0, bA0 + kb);
            ldm_x4(B1, bB0 + kb);
            if (ks < 5) {         // prefetch A for next ks
                ldm_x4(Ab[cur ^ 1][0], aX + kb + 32);
                ldm_x4(Ab[cur ^ 1][1], aX + 16 * 208 + kb + 32);
            }
            if (ks & 1) {
                // C4 held from previous step: issue its MMAs first (B0/B1 get latency slack)
                #pragma unroll
                for (int mt = 0; mt < 2; mt++)
                    mma_fp16(acc0[mt][4], Ab[cur][mt], C4 + 2);
                #pragma unroll
                for (int mt = 0; mt < 2; mt++) {
                    mma_fp16(acc0[mt][0], Ab[cur][mt], B0);
                    mma_fp16(acc0[mt][1], Ab[cur][mt], B0 + 2);
                    mma_fp16(acc0[mt][2], Ab[cur][mt], B1);
                    mma_fp16(acc0[mt][3], Ab[cur][mt], B1 + 2);
                }
            } else {
                #pragma unroll
                for (int mt = 0; mt < 2; mt++) {
                    mma_fp16(acc0[mt][0], Ab[cur][mt], B0);
                    mma_fp16(acc0[mt][1], Ab[cur][mt], B0 + 2);
                    mma_fp16(acc0[mt][2], Ab[cur][mt], B1);
                    mma_fp16(acc0[mt][3], Ab[cur][mt], B1 + 2);
                    mma_fp16(acc0[mt][4], Ab[cur][mt], C4);
                }
            }
        }
        __syncthreads();          // all reads of X/WB done before overwrite

        if (c < 3) {
            const uint4* src = g_W0img[t][c + 1];
            for (int i = tid; i < 2080; i += 256) cp16(sb + WB_OFF + i * 16, src + i);
            CP_COMMIT();
        }
    }

    // prefetch W1 half 0 into WB (overlaps epilogue 0)
    {
        const uint4* src = g_W1img[t][0];
        for (int i = tid; i < 1344; i += 256) cp16(sb + WB_OFF + i * 16, src + i);
        CP_COMMIT();
    }

    // epilogue 0 -> H0 (stride 336), packed celu
    #pragma unroll
    for (int mt = 0; mt < 2; mt++) {
        int row0 = mb + mt * 16 + (lane >> 2);
        #pragma unroll
        for (int nt = 0; nt < 5; nt++) {
            int col = nww * 40 + nt * 8 + 2 * (lane & 3);
            float* d = acc0[mt][nt];
            __half2 v01 = celu_h2(__floats2half2_rn(d[0] + sBias[col], d[1] + sBias[col + 1]));
            __half2 v23 = celu_h2(__floats2half2_rn(d[2] + sBias[col], d[3] + sBias[col + 1]));
            *(__half2*)(smem + H0_OFF + row0 * 336 + col * 2)       = v01;
            *(__half2*)(smem + H0_OFF + (row0 + 8) * 336 + col * 2) = v23;
        }
    }
    CP_WAIT(0);
    __syncthreads();

    // ===================== LAYER 1: 160 -> 128 (two 64-N halves) =====================
    const uint32_t aH0 = sb + H0_OFF + (mb + arow) * 336 + akb;
    const uint32_t bW1 = sb + WB_OFF + (nww * 16 + brow) * 336 + bkb;   // n16 per warp per half

    for (int half = 0; half < 2; half++) {
        float acc1[2][2][4];
        #pragma unroll
        for (int mt = 0; mt < 2; mt++)
            #pragma unroll
            for (int nt = 0; nt < 2; nt++)
                #pragma unroll
                for (int q = 0; q < 4; q++) acc1[mt][nt][q] = 0.f;

        uint32_t Ab[2][2][4], Bb[2][4];
        ldm_x4(Ab[0][0], aH0);
        ldm_x4(Ab[0][1], aH0 + 16 * 336);
        ldm_x4(Bb[0], bW1);
        #pragma unroll
        for (int ks = 0; ks < 10; ks++) {
            const int cur = ks & 1;
            if (ks < 9) {
                const uint32_t kb2 = (ks + 1) * 32;
                ldm_x4(Ab[cur ^ 1][0], aH0 + kb2);
                ldm_x4(Ab[cur ^ 1][1], aH0 + 16 * 336 + kb2);
                ldm_x4(Bb[cur ^ 1], bW1 + kb2);
            }
            #pragma unroll
            for (int mt = 0; mt < 2; mt++) {
                mma_fp16(acc1[mt][0], Ab[cur][mt], Bb[cur]);
                mma_fp16(acc1[mt][1], Ab[cur][mt], Bb[cur] + 2);
            }
        }

        // reordered staging: retire WB reads, issue next copy, THEN do epilogue (copy hides behind it)
        __syncthreads();              // all warps' WB reads (this half) done
        if (half == 0) {
            const uint4* src = g_W1img[t][1];
            for (int i = tid; i < 1344; i += 256) cp16(sb + WB_OFF + i * 16, src + i);
            CP_COMMIT();
        } else {
            const uint4* src = g_W2img[t];
            for (int i = tid; i < 1632; i += 256) cp16(sb + WB_OFF + i * 16, src + i);
            CP_COMMIT();
        }

        // epilogue 1 -> H1 cols [half*64 + nww*16, +16) (stride 272), packed celu
        #pragma unroll
        for (int mt = 0; mt < 2; mt++) {
            int row0 = mb + mt * 16 + (lane >> 2);
            #pragma unroll
            for (int nt = 0; nt < 2; nt++) {
                int col = half * 64 + nww * 16 + nt * 8 + 2 * (lane & 3);
                float* d = acc1[mt][nt];
                __half2 v01 = celu_h2(__floats2half2_rn(d[0] + sBias[160 + col], d[1] + sBias[160 + col + 1]));
                __half2 v23 = celu_h2(__floats2half2_rn(d[2] + sBias[160 + col], d[3] + sBias[160 + col + 1]));
                *(__half2*)(smem + H1_OFF + row0 * 272 + col * 2)       = v01;
                *(__half2*)(smem + H1_OFF + (row0 + 8) * 272 + col * 2) = v23;
            }
        }
        CP_WAIT(0);
        __syncthreads();              // next WB contents + H1 writes visible
    }

    // ===================== LAYER 2: 128 -> 96 (+ fused layer 3 & reduce) =====================
    float acc2[2][3][4];
    #pragma unroll
    for (int mt = 0; mt < 2; mt++)
        #pragma unroll
        for (int nt = 0; nt < 3; nt++)
            #pragma unroll
            for (int q = 0; q < 4; q++) acc2[mt][nt][q] = 0.f;

    const uint32_t aH1 = sb + H1_OFF + (mb + arow) * 272 + akb;
    const uint32_t bA2 = sb + WB_OFF + (nww * 24 + brow) * 272 + bkb;            // n16
    const uint32_t bC24 = sb + WB_OFF + (nww * 24 + 16 + brow2) * 272 + bkb4;    // n8 k32 (x4)

    {
        uint32_t Ab[2][2][4], Bb[2][4], C4[4];
        ldm_x4(Ab[0][0], aH1);
        ldm_x4(Ab[0][1], aH1 + 16 * 272);
        ldm_x4(Bb[0], bA2);
        #pragma unroll
        for (int ks = 0; ks < 8; ks++) {
            const int cur = ks & 1;
            if ((ks & 1) == 0) ldm_x4(C4, bC24 + (ks >> 1) * 64);   // n8 x k32
            if (ks < 7) {
                const uint32_t kb2 = (ks + 1) * 32;
                ldm_x4(Ab[cur ^ 1][0], aH1 + kb2);
                ldm_x4(Ab[cur ^ 1][1], aH1 + 16 * 272 + kb2);
                ldm_x4(Bb[cur ^ 1], bA2 + kb2);
            }
            if (ks & 1) {
                #pragma unroll
                for (int mt = 0; mt < 2; mt++)
                    mma_fp16(acc2[mt][2], Ab[cur][mt], C4 + 2);
                #pragma unroll
                for (int mt = 0; mt < 2; mt++) {
                    mma_fp16(acc2[mt][0], Ab[cur][mt], Bb[cur]);
                    mma_fp16(acc2[mt][1], Ab[cur][mt], Bb[cur] + 2);
                }
            } else {
                #pragma unroll
                for (int mt = 0; mt < 2; mt++) {
                    mma_fp16(acc2[mt][0], Ab[cur][mt], Bb[cur]);
                    mma_fp16(acc2[mt][1], Ab[cur][mt], Bb[cur] + 2);
                    mma_fp16(acc2[mt][2], Ab[cur][mt], C4);
                }
            }
        }
    }

    // layer-3 + molecule reduce: atomicAdd per-atom contribution into out_e
    {
        float part[2][2] = {{0.f, 0.f}, {0.f, 0.f}};
        #pragma unroll
        for (int mt = 0; mt < 2; mt++)
            #pragma unroll
            for (int nt = 0; nt < 3; nt++) {
                int col = nww * 24 + nt * 8 + 2 * (lane & 3);
                float* d = acc2[mt][nt];
                part[mt][0] += celu_f(d[0] + sBias[288 + col]) * sBias[384 + col]
                             + celu_f(d[1] + sBias[288 + col + 1]) * sBias[384 + col + 1];
                part[mt][1] += celu_f(d[2] + sBias[288 + col]) * sBias[384 + col]
                             + celu_f(d[3] + sBias[288 + col + 1]) * sBias[384 + col + 1];
            }
        #pragma unroll
        for (int mt = 0; mt < 2; mt++)
            #pragma unroll
            for (int h = 0; h < 2; h++) {
                part[mt][h] += __shfl_xor_sync(0xffffffffu, part[mt][h], 1);
                part[mt][h] += __shfl_xor_sync(0xffffffffu, part[mt][h], 2);
            }
        if ((lane & 3) == 0) {
            #pragma unroll
            for (int mt = 0; mt < 2; mt++)
                #pragma unroll
                for (int h = 0; h < 2; h++) {
                    int row = mb + mt * 16 + h * 8 + (lane >> 2);
                    int gi  = sIdx[row];
                    if (gi >= 0) {
                        float v = part[mt][h] + (nww == 0 ? sBias[480] : 0.f);
                        atomicAdd(out_e + (gi >> 6), v);
                    }
                }
        }
    }
}

extern "C" void kernel_launch(void* const* d_in, const int* in_sizes, int n_in,
                              void* d_out, int out_size)
{
    const int*   sp  = (const int*)d_in[0];
    const float* aev = (const float*)d_in[1];
    const float* W0 = (const float*)d_in[2];
    const float* b0 = (const float*)d_in[3];
    const float* W1 = (const float*)d_in[4];
    const float* b1 = (const float*)d_in[5];
    const float* W2 = (const float*)d_in[6];
    const float* b2 = (const float*)d_in[7];
    const float* W3 = (const float*)d_in[8];
    const float* b3 = (const float*)d_in[9];

    float* out = (float*)d_out;
    float* out_head;
    float* out_e;
    if (out_size == NB) { out_head = nullptr; out_e = out; }
    else                { out_head = out;     out_e = out + (out_size - NB); }

    k_detect<<<1, 32>>>(sp);
    k_fused <<<CP_GRID, 256>>>(sp, W0, W1, W2, out_head, out_e);

    cudaFuncSetAttribute(k_mlp_tc, cudaFuncAttributeMaxDynamicSharedMemorySize, SM_TOTAL);
    k_mlp_tc<<<MAXTILES, 256, SM_TOTAL>>>(aev, b0, b1, b2, W3, b3, out_e);
}